// round 12
// baseline (speedup 1.0000x reference)
#include <cuda_runtime.h>
#include <cuda_bf16.h>
#include <cstdint>
#include <cstddef>

#define NB 8
#define NL 512
#define ND 512
#define NH 8
#define HD 64
#define NE 4
#define NDF 2048
#define NBL 4096   // NB*NL

#define NEGINF __int_as_float(0xff800000)

// per-layer weight block (bf16, [N][K] layouts)
#define LSTRIDE 3932160
#define W_CONV 0               // [512][1536]
#define W_Q    786432          // [512][512]
#define W_K    1048576
#define W_V    1310720
#define W_O    1572864
#define W_F1   1835008         // [2048][512]
#define W_F2   2883584         // [512][2048]

// smem (bytes): padded rows of 72 bf16 = 144 B (conflict-free ldmatrix)
#define SM_AHI  0
#define SM_ALO  18432          // 128*144
#define SM_BHI  36864
#define SM_BLO  46080          // + 64*144
#define SM_SZ   55296          // one buffer
#define SM_TOT  110592         // double-buffered

// ---------------- scratch (static device allocations) ----------------
__device__ float g_h [NBL*ND];
__device__ float g_t [NBL*ND];
__device__ float g_v [NBL*ND];
__device__ float g_sc[(size_t)64*NL*NL];     // [B*H][L][L]
__device__ __nv_bfloat16 g_whi[(size_t)NE*LSTRIDE];
__device__ __nv_bfloat16 g_wlo[(size_t)NE*LSTRIDE];
__device__ __nv_bfloat16 g_hhi[NBL*ND],  g_hlo[NBL*ND];
__device__ __nv_bfloat16 g_qhi[NBL*ND],  g_qlo[NBL*ND];
__device__ __nv_bfloat16 g_khi[NBL*ND],  g_klo[NBL*ND];
__device__ __nv_bfloat16 g_aohi[NBL*ND], g_aolo[NBL*ND];
__device__ __nv_bfloat16 g_mhi[NBL*NDF], g_mlo[NBL*NDF];

// ---------------- helpers ----------------
__device__ __forceinline__ uint32_t smem_u32(const void* p) {
    uint32_t a;
    asm("{ .reg .u64 t; cvta.to.shared.u64 t, %1; cvt.u32.u64 %0, t; }" : "=r"(a) : "l"(p));
    return a;
}
__device__ __forceinline__ void ldsm4(uint32_t* r, uint32_t addr) {
    asm volatile("ldmatrix.sync.aligned.m8n8.x4.shared.b16 {%0,%1,%2,%3}, [%4];"
                 : "=r"(r[0]), "=r"(r[1]), "=r"(r[2]), "=r"(r[3]) : "r"(addr));
}
__device__ __forceinline__ void mma16816(float* c, const uint32_t* a, const uint32_t* b) {
    asm volatile(
        "mma.sync.aligned.m16n8k16.row.col.f32.bf16.bf16.f32 "
        "{%0,%1,%2,%3}, {%4,%5,%6,%7}, {%8,%9}, {%0,%1,%2,%3};"
        : "+f"(c[0]), "+f"(c[1]), "+f"(c[2]), "+f"(c[3])
        : "r"(a[0]), "r"(a[1]), "r"(a[2]), "r"(a[3]), "r"(b[0]), "r"(b[1]));
}
__device__ __forceinline__ void split2(float x, __nv_bfloat16& hi, __nv_bfloat16& lo) {
    hi = __float2bfloat16(x);
    lo = __float2bfloat16(x - __bfloat162float(hi));
}
#define CP16(dst, src, sz) \
    asm volatile("cp.async.ca.shared.global [%0], [%1], 16, %2;" \
                 :: "r"(dst), "l"(src), "r"(sz))
#define CP_COMMIT() asm volatile("cp.async.commit_group;")
#define CP_WAIT(n)  asm volatile("cp.async.wait_group %0;" :: "n"(n))

// ---------------- weight prep: transpose+split [K][N] -> [N][K] bf16 hi/lo -------------
__global__ __launch_bounds__(256) void tsplit_kernel(
    const float* __restrict__ src, __nv_bfloat16* __restrict__ hi,
    __nv_bfloat16* __restrict__ lo, int K, int N,
    size_t src_stride, size_t dst_stride)
{
    __shared__ float tile[32][33];
    int kb = blockIdx.y << 5, nb = blockIdx.x << 5;
    const float* s = src + (size_t)blockIdx.z * src_stride;
    int tx = threadIdx.x, ty = threadIdx.y;   // 32 x 8
    #pragma unroll
    for (int j = 0; j < 4; j++)
        tile[ty + j*8][tx] = s[(size_t)(kb + ty + j*8)*N + nb + tx];
    __syncthreads();
    size_t dbase = (size_t)blockIdx.z * dst_stride;
    #pragma unroll
    for (int j = 0; j < 4; j++) {
        float v = tile[tx][ty + j*8];
        __nv_bfloat16 h_, l_; split2(v, h_, l_);
        size_t o = dbase + (size_t)(nb + ty + j*8)*K + kb + tx;
        hi[o] = h_; lo[o] = l_;
    }
}

// conv weights: w[l][o][i][tap] -> dst[l-block][o][tap*512+i] bf16 hi/lo
__global__ __launch_bounds__(256) void convprep_kernel(
    const float* __restrict__ w, __nv_bfloat16* __restrict__ hi, __nv_bfloat16* __restrict__ lo)
{
    int idx = blockIdx.x * 256 + threadIdx.x;   // 4*512*1536
    int l = idx / (512*1536);
    int r = idx % (512*1536);
    int o = r / 1536;
    int k = r % 1536;
    int tap = k >> 9, i = k & 511;
    float v = w[(((size_t)l*512 + o)*512 + i)*3 + tap];
    __nv_bfloat16 h_, l_; split2(v, h_, l_);
    size_t dst = (size_t)l*LSTRIDE + (size_t)o*1536 + k;
    hi[dst] = h_; lo[dst] = l_;
}

// ---------------- input embedding (also emits bf16 split) ----------------
__global__ __launch_bounds__(256) void embed_kernel(
    const float* __restrict__ x, const float* __restrict__ tf,
    const float* __restrict__ inw, const float* __restrict__ inb,
    const float* __restrict__ pe, const float* __restrict__ tw,
    const float* __restrict__ tb, const float* __restrict__ ps,
    const float* __restrict__ ts, float* __restrict__ out,
    __nv_bfloat16* __restrict__ ohi, __nv_bfloat16* __restrict__ olo)
{
    int bl = blockIdx.x;
    int t  = threadIdx.x;
    __shared__ float xs[64];
    __shared__ float t2[2];
    if (t < 64) xs[t] = x[bl*64 + t];
    if (t < 2)  t2[t] = tf[bl*2 + t];
    __syncthreads();
    float pss = ps[0], tss = ts[0];
    int pos = bl & (NL-1);
    #pragma unroll
    for (int rep = 0; rep < 2; rep++) {
        int d = t + (rep << 8);
        float acc = inb[d];
        #pragma unroll 16
        for (int i = 0; i < 64; i++) acc += xs[i] * inw[i*ND + d];
        acc += pss * pe[pos*ND + d];
        acc += tss * (t2[0]*tw[d] + t2[1]*tw[ND + d] + tb[d]);
        out[bl*ND + d] = acc;
        __nv_bfloat16 h_, l_; split2(acc, h_, l_);
        ohi[bl*ND + d] = h_; olo[bl*ND + d] = l_;
    }
}

// ---------------- HMMA GEMM: 128x64 tile, K-chunks of 64, bf16 3-way split --------------
// cp.async double-buffered. 256 threads, 8 warps: wm = wid&3 (32 M), wn = wid>>2 (32 N).
template<int CONV, int RELU, int ADDRES, int OUTF32, int OUTSPLIT>
__device__ __forceinline__ void tgemm_body(
    const __nv_bfloat16* __restrict__ Ahi, const __nv_bfloat16* __restrict__ Alo,
    const __nv_bfloat16* __restrict__ Bhi, const __nv_bfloat16* __restrict__ Blo,
    const float* __restrict__ bias, const float* __restrict__ res,
    float* __restrict__ C, __nv_bfloat16* __restrict__ Chi, __nv_bfloat16* __restrict__ Clo,
    int N, int K, int bn, int bm)
{
    extern __shared__ char smem[];
    uint32_t sb = smem_u32(smem);
    int t = threadIdx.x;
    int lane = t & 31, wid = t >> 5;
    int wm = wid & 3, wn = wid >> 2;

    // per-thread load coordinates
    int aRow = t >> 1, aHalf = t & 1;
    int bRow = t >> 2, bQ = t & 3;
    uint32_t aSo = (uint32_t)aRow*144 + (uint32_t)aHalf*64;
    uint32_t bSo = (uint32_t)bRow*144 + (uint32_t)bQ*32;

    // ldmatrix per-lane address pieces
    int sub = lane >> 3, r8 = lane & 7;
    uint32_t aOff = (uint32_t)(wm*32 + (sub & 1)*8 + r8) * 144 + (uint32_t)(sub >> 1) * 16;
    uint32_t bOff = (uint32_t)(wn*32 + (sub >> 1)*8 + r8) * 144 + (uint32_t)(sub & 1) * 16;

    float acc[2][4][4];
    #pragma unroll
    for (int i = 0; i < 2; i++)
        #pragma unroll
        for (int j = 0; j < 4; j++)
            #pragma unroll
            for (int q = 0; q < 4; q++) acc[i][j][q] = 0.f;

    int nk = K >> 6;

    #define ISSUE_CHUNK(cc, bufsel)                                            \
    do {                                                                       \
        uint32_t sbb = sb + (uint32_t)(bufsel) * SM_SZ;                        \
        int k0_ = (cc) << 6;                                                   \
        const char *ph_, *pl_;                                                 \
        uint32_t sz_ = 16;                                                     \
        int m_ = bm + aRow;                                                    \
        if (CONV) {                                                            \
            int tap_ = k0_ >> 9;                                               \
            int i0_  = (k0_ & 511) + aHalf*32;                                 \
            int rr_  = m_ + tap_ - 2;                                          \
            if (((m_ & 511) + tap_ - 2) < 0) { sz_ = 0; rr_ = m_; }            \
            ph_ = (const char*)&Ahi[(size_t)rr_*512 + i0_];                    \
            pl_ = (const char*)&Alo[(size_t)rr_*512 + i0_];                    \
        } else {                                                               \
            ph_ = (const char*)&Ahi[(size_t)m_*K + k0_ + aHalf*32];            \
            pl_ = (const char*)&Alo[(size_t)m_*K + k0_ + aHalf*32];            \
        }                                                                      \
        _Pragma("unroll")                                                      \
        for (int u = 0; u < 4; u++) {                                          \
            CP16(sbb + SM_AHI + aSo + u*16, ph_ + u*16, sz_);                  \
            CP16(sbb + SM_ALO + aSo + u*16, pl_ + u*16, sz_);                  \
        }                                                                      \
        const char* sh_ = (const char*)&Bhi[(size_t)(bn + bRow)*K + k0_ + bQ*16]; \
        const char* sl_ = (const char*)&Blo[(size_t)(bn + bRow)*K + k0_ + bQ*16]; \
        _Pragma("unroll")                                                      \
        for (int u = 0; u < 2; u++) {                                          \
            CP16(sbb + SM_BHI + bSo + u*16, sh_ + u*16, 16u);                  \
            CP16(sbb + SM_BLO + bSo + u*16, sl_ + u*16, 16u);                  \
        }                                                                      \
        CP_COMMIT();                                                           \
    } while (0)

    ISSUE_CHUNK(0, 0);

    for (int c = 0; c < nk; c++) {
        if (c + 1 < nk) {
            ISSUE_CHUNK(c + 1, (c + 1) & 1);
            CP_WAIT(1);
        } else {
            CP_WAIT(0);
        }
        __syncthreads();

        uint32_t sbb = sb + (uint32_t)(c & 1) * SM_SZ;
        #pragma unroll
        for (int ks = 0; ks < 4; ks++) {
            uint32_t ko = ks*32;
            uint32_t ah0[4], ah1[4], al0[4], al1[4];
            uint32_t bh0[4], bh1[4], bl0[4], bl1[4];
            ldsm4(ah0, sbb + SM_AHI + aOff + ko);
            ldsm4(ah1, sbb + SM_AHI + aOff + 16*144 + ko);
            ldsm4(al0, sbb + SM_ALO + aOff + ko);
            ldsm4(al1, sbb + SM_ALO + aOff + 16*144 + ko);
            ldsm4(bh0, sbb + SM_BHI + bOff + ko);
            ldsm4(bh1, sbb + SM_BHI + bOff + 16*144 + ko);
            ldsm4(bl0, sbb + SM_BLO + bOff + ko);
            ldsm4(bl1, sbb + SM_BLO + bOff + 16*144 + ko);
            #pragma unroll
            for (int mt = 0; mt < 2; mt++) {
                const uint32_t* ah = mt ? ah1 : ah0;
                const uint32_t* al = mt ? al1 : al0;
                #pragma unroll
                for (int nt = 0; nt < 4; nt++) {
                    const uint32_t* bh = ((nt < 2) ? bh0 : bh1) + (nt & 1)*2;
                    const uint32_t* bl = ((nt < 2) ? bl0 : bl1) + (nt & 1)*2;
                    mma16816(acc[mt][nt], ah, bh);
                    mma16816(acc[mt][nt], ah, bl);
                    mma16816(acc[mt][nt], al, bh);
                }
            }
        }
        __syncthreads();
    }
    #undef ISSUE_CHUNK

    // ---- epilogue ----
    int g = lane >> 2, tc = lane & 3;
    #pragma unroll
    for (int mt = 0; mt < 2; mt++) {
        #pragma unroll
        for (int h2 = 0; h2 < 2; h2++) {
            int row = bm + wm*32 + mt*16 + h2*8 + g;
            #pragma unroll
            for (int nt = 0; nt < 4; nt++) {
                int col = bn + wn*32 + nt*8 + tc*2;
                float v0 = acc[mt][nt][h2*2+0] + bias[col];
                float v1 = acc[mt][nt][h2*2+1] + bias[col+1];
                if (RELU) { v0 = fmaxf(v0, 0.f); v1 = fmaxf(v1, 0.f); }
                if (ADDRES) {
                    float2 r2 = *(const float2*)&res[(size_t)row*N + col];
                    v0 += r2.x; v1 += r2.y;
                }
                if (OUTF32) {
                    float2 o; o.x = v0; o.y = v1;
                    *(float2*)&C[(size_t)row*N + col] = o;
                }
                if (OUTSPLIT) {
                    __nv_bfloat16 h0, l0, h1, l1;
                    split2(v0, h0, l0);
                    split2(v1, h1, l1);
                    __nv_bfloat162 hp; hp.x = h0; hp.y = h1;
                    __nv_bfloat162 lp; lp.x = l0; lp.y = l1;
                    *(__nv_bfloat162*)&Chi[(size_t)row*N + col] = hp;
                    *(__nv_bfloat162*)&Clo[(size_t)row*N + col] = lp;
                }
            }
        }
    }
}

template<int CONV, int RELU, int ADDRES, int OUTF32, int OUTSPLIT>
__global__ __launch_bounds__(256) void tgemm_kernel(
    const __nv_bfloat16* __restrict__ Ahi, const __nv_bfloat16* __restrict__ Alo,
    const __nv_bfloat16* __restrict__ Bhi, const __nv_bfloat16* __restrict__ Blo,
    const float* __restrict__ bias, const float* __restrict__ res,
    float* __restrict__ C, __nv_bfloat16* __restrict__ Chi, __nv_bfloat16* __restrict__ Clo,
    int N, int K)
{
    tgemm_body<CONV, RELU, ADDRES, OUTF32, OUTSPLIT>(
        Ahi, Alo, Bhi, Blo, bias, res, C, Chi, Clo, N, K,
        blockIdx.x << 6, blockIdx.y << 7);
}

// merged Q/K projection: blockIdx.z in {0,1}; split-only output
__global__ __launch_bounds__(256) void tgemm_qk_kernel(
    const __nv_bfloat16* __restrict__ Ahi, const __nv_bfloat16* __restrict__ Alo,
    const __nv_bfloat16* __restrict__ Whi, const __nv_bfloat16* __restrict__ Wlo,
    const float* __restrict__ b0, const float* __restrict__ b1,
    __nv_bfloat16* __restrict__ q_hi, __nv_bfloat16* __restrict__ q_lo,
    __nv_bfloat16* __restrict__ k_hi, __nv_bfloat16* __restrict__ k_lo)
{
    int z = blockIdx.z;
    const __nv_bfloat16* bh = Whi + (size_t)z * 262144;
    const __nv_bfloat16* bl = Wlo + (size_t)z * 262144;
    const float* bia = (z == 0) ? b0 : b1;
    __nv_bfloat16* chi = (z == 0) ? q_hi : k_hi;
    __nv_bfloat16* clo = (z == 0) ? q_lo : k_lo;
    tgemm_body<0, 0, 0, 0, 1>(Ahi, Alo, bh, bl, bia, nullptr, nullptr, chi, clo,
                              ND, ND, blockIdx.x << 6, blockIdx.y << 7);
}

// ---------------- fused add + LayerNorm (emits fp32 + bf16 split) ----------------
__global__ __launch_bounds__(256) void ln_kernel(
    const float* __restrict__ a, const float* __restrict__ b,
    const float* __restrict__ sc, const float* __restrict__ bi,
    float* __restrict__ out, __nv_bfloat16* __restrict__ ohi, __nv_bfloat16* __restrict__ olo)
{
    int row = blockIdx.x;
    int t = threadIdx.x;
    const float* ar = a + (size_t)row*ND;
    const float* br = b + (size_t)row*ND;
    float v0 = ar[t]       + br[t];
    float v1 = ar[t + 256] + br[t + 256];
    float s1 = v0 + v1;
    float s2 = v0*v0 + v1*v1;
    #pragma unroll
    for (int off = 16; off > 0; off >>= 1) {
        s1 += __shfl_xor_sync(0xffffffffu, s1, off);
        s2 += __shfl_xor_sync(0xffffffffu, s2, off);
    }
    __shared__ float r1[8], r2[8], mv[2];
    int w = t >> 5, lane = t & 31;
    if (lane == 0) { r1[w] = s1; r2[w] = s2; }
    __syncthreads();
    if (t == 0) {
        float a1 = 0.f, a2 = 0.f;
        #pragma unroll
        for (int i = 0; i < 8; i++) { a1 += r1[i]; a2 += r2[i]; }
        float mean = a1 * (1.f/512.f);
        float var  = a2 * (1.f/512.f) - mean*mean;
        mv[0] = mean;
        mv[1] = rsqrtf(var + 1e-5f);
    }
    __syncthreads();
    float mean = mv[0], rstd = mv[1];
    float o0 = (v0 - mean)*rstd*sc[t]       + bi[t];
    float o1 = (v1 - mean)*rstd*sc[t + 256] + bi[t + 256];
    out[(size_t)row*ND + t]       = o0;
    out[(size_t)row*ND + t + 256] = o1;
    __nv_bfloat16 h_, l_;
    split2(o0, h_, l_);
    ohi[(size_t)row*ND + t] = h_;       olo[(size_t)row*ND + t] = l_;
    split2(o1, h_, l_);
    ohi[(size_t)row*ND + t + 256] = h_; olo[(size_t)row*ND + t + 256] = l_;
}

// ---------------- scores (HMMA): per (b,h), lower-tri 64x64 tiles of q @ k^T * scale ----
// Q/K in bf16 hi/lo split; 8 warps as 4(M:16) x 2(N:32).
#define SS_QHI 0
#define SS_QLO 9216
#define SS_KHI 18432
#define SS_KLO 27648
__global__ __launch_bounds__(256) void scores_kernel(
    const __nv_bfloat16* __restrict__ q_hi, const __nv_bfloat16* __restrict__ q_lo,
    const __nv_bfloat16* __restrict__ k_hi, const __nv_bfloat16* __restrict__ k_lo,
    float* __restrict__ sc)
{
    int nt = blockIdx.x, mt = blockIdx.y, bh = blockIdx.z;
    if (nt > mt) return;
    int b = bh >> 3, h = bh & 7;
    __shared__ __align__(16) char ssm[36864];
    uint32_t sb = smem_u32(ssm);
    int t = threadIdx.x;
    int lane = t & 31, wid = t >> 5;
    int wm = wid & 3, wn = wid >> 2;

    // load 64x64 bf16 tiles (hi/lo for q and k); thread t: row=t>>2, quarter=t&3 (16 bf16)
    {
        int row = t >> 2, qq = t & 3;
        size_t qbase = ((size_t)(b*NL + mt*64 + row))*ND + h*HD + qq*16;
        size_t kbase = ((size_t)(b*NL + nt*64 + row))*ND + h*HD + qq*16;
        uint32_t so = (uint32_t)row*144 + (uint32_t)qq*32;
        *(uint4*)(ssm + SS_QHI + so)      = *(const uint4*)&q_hi[qbase];
        *(uint4*)(ssm + SS_QHI + so + 16) = *(const uint4*)&q_hi[qbase + 8];
        *(uint4*)(ssm + SS_QLO + so)      = *(const uint4*)&q_lo[qbase];
        *(uint4*)(ssm + SS_QLO + so + 16) = *(const uint4*)&q_lo[qbase + 8];
        *(uint4*)(ssm + SS_KHI + so)      = *(const uint4*)&k_hi[kbase];
        *(uint4*)(ssm + SS_KHI + so + 16) = *(const uint4*)&k_hi[kbase + 8];
        *(uint4*)(ssm + SS_KLO + so)      = *(const uint4*)&k_lo[kbase];
        *(uint4*)(ssm + SS_KLO + so + 16) = *(const uint4*)&k_lo[kbase + 8];
    }
    __syncthreads();

    int sub = lane >> 3, r8 = lane & 7;
    uint32_t aOff = (uint32_t)(wm*16 + (sub & 1)*8 + r8) * 144 + (uint32_t)(sub >> 1) * 16;
    uint32_t bOff = (uint32_t)(wn*32 + (sub >> 1)*8 + r8) * 144 + (uint32_t)(sub & 1) * 16;

    float acc[4][4];
    #pragma unroll
    for (int j = 0; j < 4; j++)
        #pragma unroll
        for (int qx = 0; qx < 4; qx++) acc[j][qx] = 0.f;

    #pragma unroll
    for (int ks = 0; ks < 4; ks++) {
        uint32_t ko = ks*32;
        uint32_t ah[4], al[4];
        uint32_t bh0[4], bh1[4], bl0[4], bl1[4];
        ldsm4(ah,  sb + SS_QHI + aOff + ko);
        ldsm4(al,  sb + SS_QLO + aOff + ko);
        ldsm4(bh0, sb + SS_KHI + bOff + ko);
        ldsm4(bh1, sb + SS_KHI + bOff + 16*144 + ko);
        ldsm4(bl0, sb + SS_KLO + bOff + ko);
        ldsm4(bl1, sb + SS_KLO + bOff + 16*144 + ko);
        #pragma unroll
        for (int ntf = 0; ntf < 4; ntf++) {
            const uint32_t* bhp = ((ntf < 2) ? bh0 : bh1) + (ntf & 1)*2;
            const uint32_t* blp = ((ntf < 2) ? bl0 : bl1) + (ntf & 1)*2;
            mma16816(acc[ntf], ah, bhp);
            mma16816(acc[ntf], ah, blp);
            mma16816(acc[ntf], al, bhp);
        }
    }

    float* base = sc + (size_t)bh*NL*NL;
    int g = lane >> 2, tc = lane & 3;
    #pragma unroll
    for (int h2 = 0; h2 < 2; h2++) {
        int m = mt*64 + wm*16 + h2*8 + g;
        #pragma unroll
        for (int ntf = 0; ntf < 4; ntf++) {
            int col = nt*64 + wn*32 + ntf*8 + tc*2;
            float2 o;
            o.x = acc[ntf][h2*2+0] * 0.125f;
            o.y = acc[ntf][h2*2+1] * 0.125f;
            *(float2*)&base[(size_t)m*NL + col] = o;
        }
    }
}

// ---------------- top-k(256) select + softmax + P@V (emits ao bf16 split) -----------
__global__ __launch_bounds__(256) void attn_kernel(
    const float* __restrict__ sc, const float* __restrict__ v,
    __nv_bfloat16* __restrict__ aohi, __nv_bfloat16* __restrict__ aolo)
{
    extern __shared__ float sm[];
    float* p  = sm;             // 32*512
    float* vt = sm + 32*512;    // 64*64
    int qt = blockIdx.x, bh = blockIdx.y;
    int b = bh >> 3, h = bh & 7;
    int t = threadIdx.x;

    const float4* s4 = (const float4*)(sc + (size_t)bh*NL*NL + (size_t)(qt*32)*NL);
    float4* p4 = (float4*)p;
    #pragma unroll
    for (int i = 0; i < 16; i++) p4[t + (i << 8)] = s4[t + (i << 8)];
    __syncthreads();

    int w = t >> 5, lane = t & 31;
    for (int rr = 0; rr < 4; rr++) {
        int r  = (w << 2) + rr;
        int qg = (qt << 5) + r;
        int nv = qg + 1;
        float    ev[16];
        unsigned uv[16];
        float    svv[16];
        #pragma unroll
        for (int ii = 0; ii < 16; ii++) {
            int j = lane + (ii << 5);
            bool val = j < nv;
            float s = val ? p[(r << 9) + j] : NEGINF;
            svv[ii] = s;
            unsigned bits = __float_as_uint(s);
            uv[ii] = val ? ((bits & 0x80000000u) ? ~bits : (bits | 0x80000000u)) : 0u;
        }
        unsigned T = 1u;
        if (nv > 256) {
            T = 0u;
            for (int bit = 31; bit >= 0; bit--) {
                unsigned cand = T | (1u << bit);
                int c = 0;
                #pragma unroll
                for (int ii = 0; ii < 16; ii++) c += (uv[ii] >= cand);
                c = __reduce_add_sync(0xffffffffu, c);
                if (c >= 256) T = cand;
            }
        }
        float m = NEGINF;
        #pragma unroll
        for (int ii = 0; ii < 16; ii++)
            if (uv[ii] >= T) m = fmaxf(m, svv[ii]);
        #pragma unroll
        for (int off = 16; off > 0; off >>= 1)
            m = fmaxf(m, __shfl_xor_sync(0xffffffffu, m, off));
        float z = 0.f;
        #pragma unroll
        for (int ii = 0; ii < 16; ii++) {
            float e = (uv[ii] >= T) ? __expf(svv[ii] - m) : 0.f;
            ev[ii] = e;
            z += e;
        }
        #pragma unroll
        for (int off = 16; off > 0; off >>= 1)
            z += __shfl_xor_sync(0xffffffffu, z, off);
        float inv = 1.f / z;
        #pragma unroll
        for (int ii = 0; ii < 16; ii++) {
            int j = lane + (ii << 5);
            p[(r << 9) + j] = ev[ii] * inv;
        }
    }
    __syncthreads();

    float acc[8] = {};
    int d = t & 63, rb = t >> 6;
    for (int jt = 0; jt < 8; jt++) {
        const float4* v4 = (const float4*)(v + ((size_t)(b*NL + (jt << 6)))*ND + (h << 6));
        float4* vt4 = (float4*)vt;
        #pragma unroll
        for (int i = 0; i < 4; i++) {
            int lin = t + (i << 8);
            int jr = lin >> 4, d4 = lin & 15;
            vt4[lin] = v4[(size_t)jr*128 + d4];
        }
        __syncthreads();
        #pragma unroll 2
        for (int j = 0; j < 64; j++) {
            float vv = vt[(j << 6) + d];
            int jj = (jt << 6) + j;
            #pragma unroll
            for (int i = 0; i < 8; i++)
                acc[i] += p[((rb + (i << 2)) << 9) + jj] * vv;
        }
        __syncthreads();
    }
    #pragma unroll
    for (int i = 0; i < 8; i++) {
        int row = (qt << 5) + rb + (i << 2);
        size_t idx = ((size_t)(b*NL + row))*ND + (h << 6) + d;
        __nv_bfloat16 h_, l_;
        split2(acc[i], h_, l_);
        aohi[idx] = h_; aolo[idx] = l_;
    }
}

// ---------------- launch ----------------
extern "C" void kernel_launch(void* const* d_in, const int* in_sizes, int n_in,
                              void* d_out, int out_size) {
    const float* x     = (const float*)d_in[0];
    const float* tf    = (const float*)d_in[1];
    const float* in_w  = (const float*)d_in[2];
    const float* in_b  = (const float*)d_in[3];
    const float* pe    = (const float*)d_in[4];
    const float* tw    = (const float*)d_in[5];
    const float* tb    = (const float*)d_in[6];
    const float* ps    = (const float*)d_in[7];
    const float* ts    = (const float*)d_in[8];
    const float* convw = (const float*)d_in[9];
    const float* convb = (const float*)d_in[10];
    const float* qw    = (const float*)d_in[11];
    const float* qb    = (const float*)d_in[12];
    const float* kw    = (const float*)d_in[13];
    const float* kb    = (const float*)d_in[14];
    const float* vw    = (const float*)d_in[15];
    const float* vb    = (const float*)d_in[16];
    const float* ow    = (const float*)d_in[17];
    const float* ob    = (const float*)d_in[18];
    const float* f1w   = (const float*)d_in[19];
    const float* f1b   = (const float*)d_in[20];
    const float* f2w   = (const float*)d_in[21];
    const float* f2b   = (const float*)d_in[22];
    const float* n1s   = (const float*)d_in[23];
    const float* n1b   = (const float*)d_in[24];
    const float* n2s   = (const float*)d_in[25];
    const float* n2b   = (const float*)d_in[26];

    float *h, *tbuf, *vv, *scb;
    __nv_bfloat16 *whi, *wlo, *hhi, *hlo, *qhi, *qlo, *khi, *klo, *aohi, *aolo, *mhi, *mlo;
    cudaGetSymbolAddress((void**)&h,    g_h);
    cudaGetSymbolAddress((void**)&tbuf, g_t);
    cudaGetSymbolAddress((void**)&vv,   g_v);
    cudaGetSymbolAddress((void**)&scb,  g_sc);
    cudaGetSymbolAddress((void**)&whi,  g_whi);
    cudaGetSymbolAddress((void**)&wlo,  g_wlo);
    cudaGetSymbolAddress((void**)&hhi,  g_hhi);
    cudaGetSymbolAddress((void**)&hlo,  g_hlo);
    cudaGetSymbolAddress((void**)&qhi,  g_qhi);
    cudaGetSymbolAddress((void**)&qlo,  g_qlo);
    cudaGetSymbolAddress((void**)&khi,  g_khi);
    cudaGetSymbolAddress((void**)&klo,  g_klo);
    cudaGetSymbolAddress((void**)&aohi, g_aohi);
    cudaGetSymbolAddress((void**)&aolo, g_aolo);
    cudaGetSymbolAddress((void**)&mhi,  g_mhi);
    cudaGetSymbolAddress((void**)&mlo,  g_mlo);

    cudaFuncSetAttribute(attn_kernel, cudaFuncAttributeMaxDynamicSharedMemorySize, 81920);
    cudaFuncSetAttribute(tgemm_kernel<1,0,0,1,0>, cudaFuncAttributeMaxDynamicSharedMemorySize, SM_TOT);
    cudaFuncSetAttribute(tgemm_kernel<0,0,0,1,0>, cudaFuncAttributeMaxDynamicSharedMemorySize, SM_TOT);
    cudaFuncSetAttribute(tgemm_kernel<0,1,0,0,1>, cudaFuncAttributeMaxDynamicSharedMemorySize, SM_TOT);
    cudaFuncSetAttribute(tgemm_kernel<0,0,1,1,1>, cudaFuncAttributeMaxDynamicSharedMemorySize, SM_TOT);
    cudaFuncSetAttribute(tgemm_kernel<0,0,1,1,0>, cudaFuncAttributeMaxDynamicSharedMemorySize, SM_TOT);
    cudaFuncSetAttribute(tgemm_qk_kernel, cudaFuncAttributeMaxDynamicSharedMemorySize, SM_TOT);

    // ---- weight prep (bf16 split, [N][K]) ----
    convprep_kernel<<<(NE*512*1536)/256, 256>>>(convw, whi, wlo);
    dim3 tb32(32, 8);
    tsplit_kernel<<<dim3(16, 16, 4), tb32>>>(qw,  whi + W_Q,  wlo + W_Q,  512,  512,  262144,  LSTRIDE);
    tsplit_kernel<<<dim3(16, 16, 4), tb32>>>(kw,  whi + W_K,  wlo + W_K,  512,  512,  262144,  LSTRIDE);
    tsplit_kernel<<<dim3(16, 16, 4), tb32>>>(vw,  whi + W_V,  wlo + W_V,  512,  512,  262144,  LSTRIDE);
    tsplit_kernel<<<dim3(16, 16, 4), tb32>>>(ow,  whi + W_O,  wlo + W_O,  512,  512,  262144,  LSTRIDE);
    tsplit_kernel<<<dim3(64, 16, 4), tb32>>>(f1w, whi + W_F1, wlo + W_F1, 512,  2048, 1048576, LSTRIDE);
    tsplit_kernel<<<dim3(16, 64, 4), tb32>>>(f2w, whi + W_F2, wlo + W_F2, 2048, 512,  1048576, LSTRIDE);

    // ---- input embedding ----
    embed_kernel<<<NBL, 256>>>(x, tf, in_w, in_b, pe, tw, tb, ps, ts, h, hhi, hlo);

    dim3 g512(8, 32);         // N=512 tiles
    dim3 gqk (8, 32, 2);
    dim3 gdf (32, 32);        // N=2048 tiles

    for (int l = 0; l < NE; l++) {
        const __nv_bfloat16* lwh = whi + (size_t)l*LSTRIDE;
        const __nv_bfloat16* lwl = wlo + (size_t)l*LSTRIDE;

        // causal conv (K=1536) -> tbuf fp32, then LN1 -> h (+split)
        tgemm_kernel<1,0,0,1,0><<<g512, 256, SM_TOT>>>(
            hhi, hlo, lwh + W_CONV, lwl + W_CONV, convb + l*ND,
            nullptr, tbuf, nullptr, nullptr, ND, 3*ND);
        ln_kernel<<<NBL, 256>>>(h, tbuf, n1s + l*ND, n1b + l*ND, h, hhi, hlo);

        // Q, K projections (split out), V projection (fp32 out)
        tgemm_qk_kernel<<<gqk, 256, SM_TOT>>>(
            hhi, hlo, lwh + W_Q, lwl + W_Q,
            qb + l*ND, kb + l*ND, qhi, qlo, khi, klo);
        tgemm_kernel<0,0,0,1,0><<<g512, 256, SM_TOT>>>(
            hhi, hlo, lwh + W_V, lwl + W_V, vb + l*ND,
            nullptr, vv, nullptr, nullptr, ND, ND);

        // scores (HMMA, lower-triangular tiles only)
        scores_kernel<<<dim3(8, 8, 64), 256>>>(qhi, qlo, khi, klo, scb);

        // top-k select + softmax + P@V -> ao split
        attn_kernel<<<dim3(16, 64), 256, 81920>>>(scb, vv, aohi, aolo);

        // output projection -> tbuf fp32, LN2 -> h (+split)
        tgemm_kernel<0,0,0,1,0><<<g512, 256, SM_TOT>>>(
            aohi, aolo, lwh + W_O, lwl + W_O, ob + l*ND,
            nullptr, tbuf, nullptr, nullptr, ND, ND);
        ln_kernel<<<NBL, 256>>>(h, tbuf, n2s + l*ND, n2b + l*ND, h, hhi, hlo);

        // FFN1: relu, split-only out
        tgemm_kernel<0,1,0,0,1><<<gdf, 256, SM_TOT>>>(
            hhi, hlo, lwh + W_F1, lwl + W_F1, f1b + l*NDF,
            nullptr, nullptr, mhi, mlo, NDF, ND);

        // FFN2: +residual h; fp32 out (+split for next layer's conv)
        if (l < NE-1) {
            tgemm_kernel<0,0,1,1,1><<<g512, 256, SM_TOT>>>(
                mhi, mlo, lwh + W_F2, lwl + W_F2, f2b + l*ND,
                h, h, hhi, hlo, ND, NDF);
        } else {
            tgemm_kernel<0,0,1,1,0><<<g512, 256, SM_TOT>>>(
                mhi, mlo, lwh + W_F2, lwl + W_F2, f2b + l*ND,
                h, (float*)d_out, nullptr, nullptr, ND, NDF);
        }
    }
}

// round 13
// speedup vs baseline: 1.6508x; 1.6508x over previous
#include <cuda_runtime.h>
#include <cuda_bf16.h>
#include <cstdint>
#include <cstddef>

#define NB 8
#define NL 512
#define ND 512
#define NH 8
#define HD 64
#define NE 4
#define NDF 2048
#define NBL 4096   // NB*NL

#define NEGINF __int_as_float(0xff800000)

// per-layer weight block (bf16, [N][K] layouts)
#define LSTRIDE 3932160
#define W_CONV 0               // [512][1536]
#define W_Q    786432          // [512][512]
#define W_K    1048576
#define W_V    1310720
#define W_O    1572864
#define W_F1   1835008         // [2048][512]
#define W_F2   2883584         // [512][2048]

// smem (bytes): padded rows of 72 bf16 = 144 B (conflict-free ldmatrix)
#define SM_AHI  0
#define SM_ALO  18432          // 128*144
#define SM_BHI  36864
#define SM_BLO  46080          // + 64*144
#define SM_SZ   55296

// ---------------- scratch (static device allocations) ----------------
__device__ float g_h [NBL*ND];
__device__ float g_t [NBL*ND];
__device__ float g_v [NBL*ND];
__device__ float g_sc[(size_t)64*NL*NL];     // [B*H][L][L]
__device__ __nv_bfloat16 g_whi[(size_t)NE*LSTRIDE];
__device__ __nv_bfloat16 g_wlo[(size_t)NE*LSTRIDE];
__device__ __nv_bfloat16 g_hhi[NBL*ND],  g_hlo[NBL*ND];
__device__ __nv_bfloat16 g_qhi[NBL*ND],  g_qlo[NBL*ND];
__device__ __nv_bfloat16 g_khi[NBL*ND],  g_klo[NBL*ND];
__device__ __nv_bfloat16 g_aohi[NBL*ND], g_aolo[NBL*ND];
__device__ __nv_bfloat16 g_mhi[NBL*NDF], g_mlo[NBL*NDF];

// ---------------- helpers ----------------
__device__ __forceinline__ uint32_t smem_u32(const void* p) {
    uint32_t a;
    asm("{ .reg .u64 t; cvta.to.shared.u64 t, %1; cvt.u32.u64 %0, t; }" : "=r"(a) : "l"(p));
    return a;
}
__device__ __forceinline__ void ldsm4(uint32_t* r, uint32_t addr) {
    asm volatile("ldmatrix.sync.aligned.m8n8.x4.shared.b16 {%0,%1,%2,%3}, [%4];"
                 : "=r"(r[0]), "=r"(r[1]), "=r"(r[2]), "=r"(r[3]) : "r"(addr));
}
__device__ __forceinline__ void mma16816(float* c, const uint32_t* a, const uint32_t* b) {
    asm volatile(
        "mma.sync.aligned.m16n8k16.row.col.f32.bf16.bf16.f32 "
        "{%0,%1,%2,%3}, {%4,%5,%6,%7}, {%8,%9}, {%0,%1,%2,%3};"
        : "+f"(c[0]), "+f"(c[1]), "+f"(c[2]), "+f"(c[3])
        : "r"(a[0]), "r"(a[1]), "r"(a[2]), "r"(a[3]), "r"(b[0]), "r"(b[1]));
}
__device__ __forceinline__ void split2(float x, __nv_bfloat16& hi, __nv_bfloat16& lo) {
    hi = __float2bfloat16(x);
    lo = __float2bfloat16(x - __bfloat162float(hi));
}

// ---------------- weight prep: transpose+split [K][N] -> [N][K] bf16 hi/lo -------------
__global__ __launch_bounds__(256) void tsplit_kernel(
    const float* __restrict__ src, __nv_bfloat16* __restrict__ hi,
    __nv_bfloat16* __restrict__ lo, int K, int N,
    size_t src_stride, size_t dst_stride)
{
    __shared__ float tile[32][33];
    int kb = blockIdx.y << 5, nb = blockIdx.x << 5;
    const float* s = src + (size_t)blockIdx.z * src_stride;
    int tx = threadIdx.x, ty = threadIdx.y;   // 32 x 8
    #pragma unroll
    for (int j = 0; j < 4; j++)
        tile[ty + j*8][tx] = s[(size_t)(kb + ty + j*8)*N + nb + tx];
    __syncthreads();
    size_t dbase = (size_t)blockIdx.z * dst_stride;
    #pragma unroll
    for (int j = 0; j < 4; j++) {
        float v = tile[tx][ty + j*8];
        __nv_bfloat16 h_, l_; split2(v, h_, l_);
        size_t o = dbase + (size_t)(nb + ty + j*8)*K + kb + tx;
        hi[o] = h_; lo[o] = l_;
    }
}

// conv weights: w[l][o][i][tap] -> dst[l-block][o][tap*512+i] bf16 hi/lo
__global__ __launch_bounds__(256) void convprep_kernel(
    const float* __restrict__ w, __nv_bfloat16* __restrict__ hi, __nv_bfloat16* __restrict__ lo)
{
    int idx = blockIdx.x * 256 + threadIdx.x;   // 4*512*1536
    int l = idx / (512*1536);
    int r = idx % (512*1536);
    int o = r / 1536;
    int k = r % 1536;
    int tap = k >> 9, i = k & 511;
    float v = w[(((size_t)l*512 + o)*512 + i)*3 + tap];
    __nv_bfloat16 h_, l_; split2(v, h_, l_);
    size_t dst = (size_t)l*LSTRIDE + (size_t)o*1536 + k;
    hi[dst] = h_; lo[dst] = l_;
}

// ---------------- input embedding (also emits bf16 split) ----------------
__global__ __launch_bounds__(256) void embed_kernel(
    const float* __restrict__ x, const float* __restrict__ tf,
    const float* __restrict__ inw, const float* __restrict__ inb,
    const float* __restrict__ pe, const float* __restrict__ tw,
    const float* __restrict__ tb, const float* __restrict__ ps,
    const float* __restrict__ ts, float* __restrict__ out,
    __nv_bfloat16* __restrict__ ohi, __nv_bfloat16* __restrict__ olo)
{
    int bl = blockIdx.x;
    int t  = threadIdx.x;
    __shared__ float xs[64];
    __shared__ float t2[2];
    if (t < 64) xs[t] = x[bl*64 + t];
    if (t < 2)  t2[t] = tf[bl*2 + t];
    __syncthreads();
    float pss = ps[0], tss = ts[0];
    int pos = bl & (NL-1);
    #pragma unroll
    for (int rep = 0; rep < 2; rep++) {
        int d = t + (rep << 8);
        float acc = inb[d];
        #pragma unroll 16
        for (int i = 0; i < 64; i++) acc += xs[i] * inw[i*ND + d];
        acc += pss * pe[pos*ND + d];
        acc += tss * (t2[0]*tw[d] + t2[1]*tw[ND + d] + tb[d]);
        out[bl*ND + d] = acc;
        __nv_bfloat16 h_, l_; split2(acc, h_, l_);
        ohi[bl*ND + d] = h_; olo[bl*ND + d] = l_;
    }
}

// ---------------- HMMA GEMM: 128x64 tile, K-chunks of 64, bf16 3-way split --------------
// Register-prefetch pipelined: LDG chunk c+1 into regs while MMAs run on chunk c.
// 256 threads, 8 warps: wm = wid&3 (32 M-rows), wn = wid>>2 (32 N-cols).
template<int CONV, int RELU, int ADDRES, int OUTF32, int OUTSPLIT>
__device__ __forceinline__ void tgemm_body(
    const __nv_bfloat16* __restrict__ Ahi, const __nv_bfloat16* __restrict__ Alo,
    const __nv_bfloat16* __restrict__ Bhi, const __nv_bfloat16* __restrict__ Blo,
    const float* __restrict__ bias, const float* __restrict__ res,
    float* __restrict__ C, __nv_bfloat16* __restrict__ Chi, __nv_bfloat16* __restrict__ Clo,
    int N, int K, int bn, int bm)
{
    extern __shared__ char smem[];
    uint32_t sb = smem_u32(smem);
    int t = threadIdx.x;
    int lane = t & 31, wid = t >> 5;
    int wm = wid & 3, wn = wid >> 2;

    // per-thread load coordinates
    int aRow = t >> 1, aHalf = t & 1;
    int bRow = t >> 2, bQ = t & 3;
    uint32_t aSo = (uint32_t)aRow*144 + (uint32_t)aHalf*64;
    uint32_t bSo = (uint32_t)bRow*144 + (uint32_t)bQ*32;

    // ldmatrix per-lane address pieces
    int sub = lane >> 3, r8 = lane & 7;
    uint32_t aOff = (uint32_t)(wm*32 + (sub & 1)*8 + r8) * 144 + (uint32_t)(sub >> 1) * 16;
    uint32_t bOff = (uint32_t)(wn*32 + (sub >> 1)*8 + r8) * 144 + (uint32_t)(sub & 1) * 16;

    float acc[2][4][4];
    #pragma unroll
    for (int i = 0; i < 2; i++)
        #pragma unroll
        for (int j = 0; j < 4; j++)
            #pragma unroll
            for (int q = 0; q < 4; q++) acc[i][j][q] = 0.f;

    int nk = K >> 6;
    uint4 pa[8];   // A: 4 hi + 4 lo
    uint4 pb[4];   // B: 2 hi + 2 lo

    #define LOAD_REGS(cc)                                                      \
    do {                                                                       \
        int k0_ = (cc) << 6;                                                   \
        const uint4 *ph_, *pl_;                                                \
        bool zero_ = false;                                                    \
        int m_ = bm + aRow;                                                    \
        if (CONV) {                                                            \
            int tap_ = k0_ >> 9;                                               \
            int i0_  = (k0_ & 511) + aHalf*32;                                 \
            zero_ = ((m_ & 511) + tap_ - 2) < 0;                               \
            int rr_ = zero_ ? m_ : (m_ + tap_ - 2);                            \
            ph_ = (const uint4*)&Ahi[(size_t)rr_*512 + i0_];                   \
            pl_ = (const uint4*)&Alo[(size_t)rr_*512 + i0_];                   \
        } else {                                                               \
            ph_ = (const uint4*)&Ahi[(size_t)m_*K + k0_ + aHalf*32];           \
            pl_ = (const uint4*)&Alo[(size_t)m_*K + k0_ + aHalf*32];           \
        }                                                                      \
        _Pragma("unroll")                                                      \
        for (int u = 0; u < 4; u++) {                                          \
            if (zero_) { pa[u] = make_uint4(0,0,0,0); pa[u+4] = make_uint4(0,0,0,0); } \
            else       { pa[u] = ph_[u]; pa[u+4] = pl_[u]; }                   \
        }                                                                      \
        const uint4* sh_ = (const uint4*)&Bhi[(size_t)(bn + bRow)*K + k0_ + bQ*16]; \
        const uint4* sl_ = (const uint4*)&Blo[(size_t)(bn + bRow)*K + k0_ + bQ*16]; \
        pb[0] = sh_[0]; pb[1] = sh_[1]; pb[2] = sl_[0]; pb[3] = sl_[1];        \
    } while (0)

    LOAD_REGS(0);

    for (int c = 0; c < nk; c++) {
        // store prefetched regs to smem
        #pragma unroll
        for (int u = 0; u < 4; u++) {
            *(uint4*)(smem + SM_AHI + aSo + u*16) = pa[u];
            *(uint4*)(smem + SM_ALO + aSo + u*16) = pa[u+4];
        }
        *(uint4*)(smem + SM_BHI + bSo)      = pb[0];
        *(uint4*)(smem + SM_BHI + bSo + 16) = pb[1];
        *(uint4*)(smem + SM_BLO + bSo)      = pb[2];
        *(uint4*)(smem + SM_BLO + bSo + 16) = pb[3];
        __syncthreads();

        // issue next chunk's global loads (latency hidden behind MMA phase)
        if (c + 1 < nk) LOAD_REGS(c + 1);

        #pragma unroll
        for (int ks = 0; ks < 4; ks++) {
            uint32_t ko = ks*32;
            uint32_t ah0[4], ah1[4], al0[4], al1[4];
            uint32_t bh0[4], bh1[4], bl0[4], bl1[4];
            ldsm4(ah0, sb + SM_AHI + aOff + ko);
            ldsm4(ah1, sb + SM_AHI + aOff + 16*144 + ko);
            ldsm4(al0, sb + SM_ALO + aOff + ko);
            ldsm4(al1, sb + SM_ALO + aOff + 16*144 + ko);
            ldsm4(bh0, sb + SM_BHI + bOff + ko);
            ldsm4(bh1, sb + SM_BHI + bOff + 16*144 + ko);
            ldsm4(bl0, sb + SM_BLO + bOff + ko);
            ldsm4(bl1, sb + SM_BLO + bOff + 16*144 + ko);
            #pragma unroll
            for (int mt = 0; mt < 2; mt++) {
                const uint32_t* ah = mt ? ah1 : ah0;
                const uint32_t* al = mt ? al1 : al0;
                #pragma unroll
                for (int nt = 0; nt < 4; nt++) {
                    const uint32_t* bh = ((nt < 2) ? bh0 : bh1) + (nt & 1)*2;
                    const uint32_t* bl = ((nt < 2) ? bl0 : bl1) + (nt & 1)*2;
                    mma16816(acc[mt][nt], ah, bh);
                    mma16816(acc[mt][nt], ah, bl);
                    mma16816(acc[mt][nt], al, bh);
                }
            }
        }
        __syncthreads();
    }
    #undef LOAD_REGS

    // ---- epilogue ----
    int g = lane >> 2, tc = lane & 3;
    #pragma unroll
    for (int mt = 0; mt < 2; mt++) {
        #pragma unroll
        for (int h2 = 0; h2 < 2; h2++) {
            int row = bm + wm*32 + mt*16 + h2*8 + g;
            #pragma unroll
            for (int nt = 0; nt < 4; nt++) {
                int col = bn + wn*32 + nt*8 + tc*2;
                float v0 = acc[mt][nt][h2*2+0] + bias[col];
                float v1 = acc[mt][nt][h2*2+1] + bias[col+1];
                if (RELU) { v0 = fmaxf(v0, 0.f); v1 = fmaxf(v1, 0.f); }
                if (ADDRES) {
                    float2 r2 = *(const float2*)&res[(size_t)row*N + col];
                    v0 += r2.x; v1 += r2.y;
                }
                if (OUTF32) {
                    float2 o; o.x = v0; o.y = v1;
                    *(float2*)&C[(size_t)row*N + col] = o;
                }
                if (OUTSPLIT) {
                    __nv_bfloat16 h0, l0, h1, l1;
                    split2(v0, h0, l0);
                    split2(v1, h1, l1);
                    __nv_bfloat162 hp; hp.x = h0; hp.y = h1;
                    __nv_bfloat162 lp; lp.x = l0; lp.y = l1;
                    *(__nv_bfloat162*)&Chi[(size_t)row*N + col] = hp;
                    *(__nv_bfloat162*)&Clo[(size_t)row*N + col] = lp;
                }
            }
        }
    }
}

template<int CONV, int RELU, int ADDRES, int OUTF32, int OUTSPLIT>
__global__ __launch_bounds__(256) void tgemm_kernel(
    const __nv_bfloat16* __restrict__ Ahi, const __nv_bfloat16* __restrict__ Alo,
    const __nv_bfloat16* __restrict__ Bhi, const __nv_bfloat16* __restrict__ Blo,
    const float* __restrict__ bias, const float* __restrict__ res,
    float* __restrict__ C, __nv_bfloat16* __restrict__ Chi, __nv_bfloat16* __restrict__ Clo,
    int N, int K)
{
    tgemm_body<CONV, RELU, ADDRES, OUTF32, OUTSPLIT>(
        Ahi, Alo, Bhi, Blo, bias, res, C, Chi, Clo, N, K,
        blockIdx.x << 6, blockIdx.y << 7);
}

// merged Q/K projection: blockIdx.z in {0,1}; split-only output
__global__ __launch_bounds__(256) void tgemm_qk_kernel(
    const __nv_bfloat16* __restrict__ Ahi, const __nv_bfloat16* __restrict__ Alo,
    const __nv_bfloat16* __restrict__ Whi, const __nv_bfloat16* __restrict__ Wlo,
    const float* __restrict__ b0, const float* __restrict__ b1,
    __nv_bfloat16* __restrict__ q_hi, __nv_bfloat16* __restrict__ q_lo,
    __nv_bfloat16* __restrict__ k_hi, __nv_bfloat16* __restrict__ k_lo)
{
    int z = blockIdx.z;
    const __nv_bfloat16* bh = Whi + (size_t)z * 262144;
    const __nv_bfloat16* bl = Wlo + (size_t)z * 262144;
    const float* bia = (z == 0) ? b0 : b1;
    __nv_bfloat16* chi = (z == 0) ? q_hi : k_hi;
    __nv_bfloat16* clo = (z == 0) ? q_lo : k_lo;
    tgemm_body<0, 0, 0, 0, 1>(Ahi, Alo, bh, bl, bia, nullptr, nullptr, chi, clo,
                              ND, ND, blockIdx.x << 6, blockIdx.y << 7);
}

// ---------------- fused add + LayerNorm (emits fp32 + bf16 split) ----------------
__global__ __launch_bounds__(256) void ln_kernel(
    const float* __restrict__ a, const float* __restrict__ b,
    const float* __restrict__ sc, const float* __restrict__ bi,
    float* __restrict__ out, __nv_bfloat16* __restrict__ ohi, __nv_bfloat16* __restrict__ olo)
{
    int row = blockIdx.x;
    int t = threadIdx.x;
    const float* ar = a + (size_t)row*ND;
    const float* br = b + (size_t)row*ND;
    float v0 = ar[t]       + br[t];
    float v1 = ar[t + 256] + br[t + 256];
    float s1 = v0 + v1;
    float s2 = v0*v0 + v1*v1;
    #pragma unroll
    for (int off = 16; off > 0; off >>= 1) {
        s1 += __shfl_xor_sync(0xffffffffu, s1, off);
        s2 += __shfl_xor_sync(0xffffffffu, s2, off);
    }
    __shared__ float r1[8], r2[8], mv[2];
    int w = t >> 5, lane = t & 31;
    if (lane == 0) { r1[w] = s1; r2[w] = s2; }
    __syncthreads();
    if (t == 0) {
        float a1 = 0.f, a2 = 0.f;
        #pragma unroll
        for (int i = 0; i < 8; i++) { a1 += r1[i]; a2 += r2[i]; }
        float mean = a1 * (1.f/512.f);
        float var  = a2 * (1.f/512.f) - mean*mean;
        mv[0] = mean;
        mv[1] = rsqrtf(var + 1e-5f);
    }
    __syncthreads();
    float mean = mv[0], rstd = mv[1];
    float o0 = (v0 - mean)*rstd*sc[t]       + bi[t];
    float o1 = (v1 - mean)*rstd*sc[t + 256] + bi[t + 256];
    out[(size_t)row*ND + t]       = o0;
    out[(size_t)row*ND + t + 256] = o1;
    __nv_bfloat16 h_, l_;
    split2(o0, h_, l_);
    ohi[(size_t)row*ND + t] = h_;       olo[(size_t)row*ND + t] = l_;
    split2(o1, h_, l_);
    ohi[(size_t)row*ND + t + 256] = h_; olo[(size_t)row*ND + t + 256] = l_;
}

// ---------------- scores (HMMA): per (b,h), lower-tri 64x64 tiles of q @ k^T * scale ----
// Q/K in bf16 hi/lo split; 8 warps as 4(M:16) x 2(N:32).
#define SS_QHI 0
#define SS_QLO 9216
#define SS_KHI 18432
#define SS_KLO 27648
__global__ __launch_bounds__(256) void scores_kernel(
    const __nv_bfloat16* __restrict__ q_hi, const __nv_bfloat16* __restrict__ q_lo,
    const __nv_bfloat16* __restrict__ k_hi, const __nv_bfloat16* __restrict__ k_lo,
    float* __restrict__ sc)
{
    int nt = blockIdx.x, mt = blockIdx.y, bh = blockIdx.z;
    if (nt > mt) return;
    int b = bh >> 3, h = bh & 7;
    __shared__ __align__(16) char ssm[36864];
    uint32_t sb = smem_u32(ssm);
    int t = threadIdx.x;
    int lane = t & 31, wid = t >> 5;
    int wm = wid & 3, wn = wid >> 2;

    // load 64x64 bf16 tiles (hi/lo for q and k); thread t: row=t>>2, quarter=t&3 (16 bf16)
    {
        int row = t >> 2, qq = t & 3;
        size_t qbase = ((size_t)(b*NL + mt*64 + row))*ND + h*HD + qq*16;
        size_t kbase = ((size_t)(b*NL + nt*64 + row))*ND + h*HD + qq*16;
        uint32_t so = (uint32_t)row*144 + (uint32_t)qq*32;
        *(uint4*)(ssm + SS_QHI + so)      = *(const uint4*)&q_hi[qbase];
        *(uint4*)(ssm + SS_QHI + so + 16) = *(const uint4*)&q_hi[qbase + 8];
        *(uint4*)(ssm + SS_QLO + so)      = *(const uint4*)&q_lo[qbase];
        *(uint4*)(ssm + SS_QLO + so + 16) = *(const uint4*)&q_lo[qbase + 8];
        *(uint4*)(ssm + SS_KHI + so)      = *(const uint4*)&k_hi[kbase];
        *(uint4*)(ssm + SS_KHI + so + 16) = *(const uint4*)&k_hi[kbase + 8];
        *(uint4*)(ssm + SS_KLO + so)      = *(const uint4*)&k_lo[kbase];
        *(uint4*)(ssm + SS_KLO + so + 16) = *(const uint4*)&k_lo[kbase + 8];
    }
    __syncthreads();

    int sub = lane >> 3, r8 = lane & 7;
    uint32_t aOff = (uint32_t)(wm*16 + (sub & 1)*8 + r8) * 144 + (uint32_t)(sub >> 1) * 16;
    uint32_t bOff = (uint32_t)(wn*32 + (sub >> 1)*8 + r8) * 144 + (uint32_t)(sub & 1) * 16;

    float acc[4][4];
    #pragma unroll
    for (int j = 0; j < 4; j++)
        #pragma unroll
        for (int qx = 0; qx < 4; qx++) acc[j][qx] = 0.f;

    #pragma unroll
    for (int ks = 0; ks < 4; ks++) {
        uint32_t ko = ks*32;
        uint32_t ah[4], al[4];
        uint32_t bh0[4], bh1[4], bl0[4], bl1[4];
        ldsm4(ah,  sb + SS_QHI + aOff + ko);
        ldsm4(al,  sb + SS_QLO + aOff + ko);
        ldsm4(bh0, sb + SS_KHI + bOff + ko);
        ldsm4(bh1, sb + SS_KHI + bOff + 16*144 + ko);
        ldsm4(bl0, sb + SS_KLO + bOff + ko);
        ldsm4(bl1, sb + SS_KLO + bOff + 16*144 + ko);
        #pragma unroll
        for (int ntf = 0; ntf < 4; ntf++) {
            const uint32_t* bhp = ((ntf < 2) ? bh0 : bh1) + (ntf & 1)*2;
            const uint32_t* blp = ((ntf < 2) ? bl0 : bl1) + (ntf & 1)*2;
            mma16816(acc[ntf], ah, bhp);
            mma16816(acc[ntf], ah, blp);
            mma16816(acc[ntf], al, bhp);
        }
    }

    float* base = sc + (size_t)bh*NL*NL;
    int g = lane >> 2, tc = lane & 3;
    #pragma unroll
    for (int h2 = 0; h2 < 2; h2++) {
        int m = mt*64 + wm*16 + h2*8 + g;
        #pragma unroll
        for (int ntf = 0; ntf < 4; ntf++) {
            int col = nt*64 + wn*32 + ntf*8 + tc*2;
            float2 o;
            o.x = acc[ntf][h2*2+0] * 0.125f;
            o.y = acc[ntf][h2*2+1] * 0.125f;
            *(float2*)&base[(size_t)m*NL + col] = o;
        }
    }
}

// ---------------- top-k(256) select + softmax + P@V (emits ao bf16 split) -----------
__global__ __launch_bounds__(256) void attn_kernel(
    const float* __restrict__ sc, const float* __restrict__ v,
    __nv_bfloat16* __restrict__ aohi, __nv_bfloat16* __restrict__ aolo)
{
    extern __shared__ float sm[];
    float* p  = sm;             // 32*512
    float* vt = sm + 32*512;    // 64*64
    int qt = blockIdx.x, bh = blockIdx.y;
    int b = bh >> 3, h = bh & 7;
    int t = threadIdx.x;

    const float4* s4 = (const float4*)(sc + (size_t)bh*NL*NL + (size_t)(qt*32)*NL);
    float4* p4 = (float4*)p;
    #pragma unroll
    for (int i = 0; i < 16; i++) p4[t + (i << 8)] = s4[t + (i << 8)];
    __syncthreads();

    int w = t >> 5, lane = t & 31;
    for (int rr = 0; rr < 4; rr++) {
        int r  = (w << 2) + rr;
        int qg = (qt << 5) + r;
        int nv = qg + 1;
        float    ev[16];
        unsigned uv[16];
        float    svv[16];
        #pragma unroll
        for (int ii = 0; ii < 16; ii++) {
            int j = lane + (ii << 5);
            bool val = j < nv;
            float s = val ? p[(r << 9) + j] : NEGINF;
            svv[ii] = s;
            unsigned bits = __float_as_uint(s);
            uv[ii] = val ? ((bits & 0x80000000u) ? ~bits : (bits | 0x80000000u)) : 0u;
        }
        unsigned T = 1u;
        if (nv > 256) {
            T = 0u;
            for (int bit = 31; bit >= 0; bit--) {
                unsigned cand = T | (1u << bit);
                int c = 0;
                #pragma unroll
                for (int ii = 0; ii < 16; ii++) c += (uv[ii] >= cand);
                c = __reduce_add_sync(0xffffffffu, c);
                if (c >= 256) T = cand;
            }
        }
        float m = NEGINF;
        #pragma unroll
        for (int ii = 0; ii < 16; ii++)
            if (uv[ii] >= T) m = fmaxf(m, svv[ii]);
        #pragma unroll
        for (int off = 16; off > 0; off >>= 1)
            m = fmaxf(m, __shfl_xor_sync(0xffffffffu, m, off));
        float z = 0.f;
        #pragma unroll
        for (int ii = 0; ii < 16; ii++) {
            float e = (uv[ii] >= T) ? __expf(svv[ii] - m) : 0.f;
            ev[ii] = e;
            z += e;
        }
        #pragma unroll
        for (int off = 16; off > 0; off >>= 1)
            z += __shfl_xor_sync(0xffffffffu, z, off);
        float inv = 1.f / z;
        #pragma unroll
        for (int ii = 0; ii < 16; ii++) {
            int j = lane + (ii << 5);
            p[(r << 9) + j] = ev[ii] * inv;
        }
    }
    __syncthreads();

    float acc[8] = {};
    int d = t & 63, rb = t >> 6;
    for (int jt = 0; jt < 8; jt++) {
        const float4* v4 = (const float4*)(v + ((size_t)(b*NL + (jt << 6)))*ND + (h << 6));
        float4* vt4 = (float4*)vt;
        #pragma unroll
        for (int i = 0; i < 4; i++) {
            int lin = t + (i << 8);
            int jr = lin >> 4, d4 = lin & 15;
            vt4[lin] = v4[(size_t)jr*128 + d4];
        }
        __syncthreads();
        #pragma unroll 2
        for (int j = 0; j < 64; j++) {
            float vv = vt[(j << 6) + d];
            int jj = (jt << 6) + j;
            #pragma unroll
            for (int i = 0; i < 8; i++)
                acc[i] += p[((rb + (i << 2)) << 9) + jj] * vv;
        }
        __syncthreads();
    }
    #pragma unroll
    for (int i = 0; i < 8; i++) {
        int row = (qt << 5) + rb + (i << 2);
        size_t idx = ((size_t)(b*NL + row))*ND + (h << 6) + d;
        __nv_bfloat16 h_, l_;
        split2(acc[i], h_, l_);
        aohi[idx] = h_; aolo[idx] = l_;
    }
}

// ---------------- launch ----------------
extern "C" void kernel_launch(void* const* d_in, const int* in_sizes, int n_in,
                              void* d_out, int out_size) {
    const float* x     = (const float*)d_in[0];
    const float* tf    = (const float*)d_in[1];
    const float* in_w  = (const float*)d_in[2];
    const float* in_b  = (const float*)d_in[3];
    const float* pe    = (const float*)d_in[4];
    const float* tw    = (const float*)d_in[5];
    const float* tb    = (const float*)d_in[6];
    const float* ps    = (const float*)d_in[7];
    const float* ts    = (const float*)d_in[8];
    const float* convw = (const float*)d_in[9];
    const float* convb = (const float*)d_in[10];
    const float* qw    = (const float*)d_in[11];
    const float* qb    = (const float*)d_in[12];
    const float* kw    = (const float*)d_in[13];
    const float* kb    = (const float*)d_in[14];
    const float* vw    = (const float*)d_in[15];
    const float* vb    = (const float*)d_in[16];
    const float* ow    = (const float*)d_in[17];
    const float* ob    = (const float*)d_in[18];
    const float* f1w   = (const float*)d_in[19];
    const float* f1b   = (const float*)d_in[20];
    const float* f2w   = (const float*)d_in[21];
    const float* f2b   = (const float*)d_in[22];
    const float* n1s   = (const float*)d_in[23];
    const float* n1b   = (const float*)d_in[24];
    const float* n2s   = (const float*)d_in[25];
    const float* n2b   = (const float*)d_in[26];

    float *h, *tbuf, *vv, *scb;
    __nv_bfloat16 *whi, *wlo, *hhi, *hlo, *qhi, *qlo, *khi, *klo, *aohi, *aolo, *mhi, *mlo;
    cudaGetSymbolAddress((void**)&h,    g_h);
    cudaGetSymbolAddress((void**)&tbuf, g_t);
    cudaGetSymbolAddress((void**)&vv,   g_v);
    cudaGetSymbolAddress((void**)&scb,  g_sc);
    cudaGetSymbolAddress((void**)&whi,  g_whi);
    cudaGetSymbolAddress((void**)&wlo,  g_wlo);
    cudaGetSymbolAddress((void**)&hhi,  g_hhi);
    cudaGetSymbolAddress((void**)&hlo,  g_hlo);
    cudaGetSymbolAddress((void**)&qhi,  g_qhi);
    cudaGetSymbolAddress((void**)&qlo,  g_qlo);
    cudaGetSymbolAddress((void**)&khi,  g_khi);
    cudaGetSymbolAddress((void**)&klo,  g_klo);
    cudaGetSymbolAddress((void**)&aohi, g_aohi);
    cudaGetSymbolAddress((void**)&aolo, g_aolo);
    cudaGetSymbolAddress((void**)&mhi,  g_mhi);
    cudaGetSymbolAddress((void**)&mlo,  g_mlo);

    cudaFuncSetAttribute(attn_kernel, cudaFuncAttributeMaxDynamicSharedMemorySize, 81920);
    cudaFuncSetAttribute(tgemm_kernel<1,0,0,1,0>, cudaFuncAttributeMaxDynamicSharedMemorySize, SM_SZ);
    cudaFuncSetAttribute(tgemm_kernel<0,0,0,1,0>, cudaFuncAttributeMaxDynamicSharedMemorySize, SM_SZ);
    cudaFuncSetAttribute(tgemm_kernel<0,1,0,0,1>, cudaFuncAttributeMaxDynamicSharedMemorySize, SM_SZ);
    cudaFuncSetAttribute(tgemm_kernel<0,0,1,1,1>, cudaFuncAttributeMaxDynamicSharedMemorySize, SM_SZ);
    cudaFuncSetAttribute(tgemm_kernel<0,0,1,1,0>, cudaFuncAttributeMaxDynamicSharedMemorySize, SM_SZ);
    cudaFuncSetAttribute(tgemm_qk_kernel, cudaFuncAttributeMaxDynamicSharedMemorySize, SM_SZ);

    // ---- weight prep (bf16 split, [N][K]) ----
    convprep_kernel<<<(NE*512*1536)/256, 256>>>(convw, whi, wlo);
    dim3 tb32(32, 8);
    tsplit_kernel<<<dim3(16, 16, 4), tb32>>>(qw,  whi + W_Q,  wlo + W_Q,  512,  512,  262144,  LSTRIDE);
    tsplit_kernel<<<dim3(16, 16, 4), tb32>>>(kw,  whi + W_K,  wlo + W_K,  512,  512,  262144,  LSTRIDE);
    tsplit_kernel<<<dim3(16, 16, 4), tb32>>>(vw,  whi + W_V,  wlo + W_V,  512,  512,  262144,  LSTRIDE);
    tsplit_kernel<<<dim3(16, 16, 4), tb32>>>(ow,  whi + W_O,  wlo + W_O,  512,  512,  262144,  LSTRIDE);
    tsplit_kernel<<<dim3(64, 16, 4), tb32>>>(f1w, whi + W_F1, wlo + W_F1, 512,  2048, 1048576, LSTRIDE);
    tsplit_kernel<<<dim3(16, 64, 4), tb32>>>(f2w, whi + W_F2, wlo + W_F2, 2048, 512,  1048576, LSTRIDE);

    // ---- input embedding ----
    embed_kernel<<<NBL, 256>>>(x, tf, in_w, in_b, pe, tw, tb, ps, ts, h, hhi, hlo);

    dim3 g512(8, 32);         // N=512 tiles
    dim3 gqk (8, 32, 2);
    dim3 gdf (32, 32);        // N=2048 tiles

    for (int l = 0; l < NE; l++) {
        const __nv_bfloat16* lwh = whi + (size_t)l*LSTRIDE;
        const __nv_bfloat16* lwl = wlo + (size_t)l*LSTRIDE;

        // causal conv (K=1536) -> tbuf fp32, then LN1 -> h (+split)
        tgemm_kernel<1,0,0,1,0><<<g512, 256, SM_SZ>>>(
            hhi, hlo, lwh + W_CONV, lwl + W_CONV, convb + l*ND,
            nullptr, tbuf, nullptr, nullptr, ND, 3*ND);
        ln_kernel<<<NBL, 256>>>(h, tbuf, n1s + l*ND, n1b + l*ND, h, hhi, hlo);

        // Q, K projections (split out), V projection (fp32 out)
        tgemm_qk_kernel<<<gqk, 256, SM_SZ>>>(
            hhi, hlo, lwh + W_Q, lwl + W_Q,
            qb + l*ND, kb + l*ND, qhi, qlo, khi, klo);
        tgemm_kernel<0,0,0,1,0><<<g512, 256, SM_SZ>>>(
            hhi, hlo, lwh + W_V, lwl + W_V, vb + l*ND,
            nullptr, vv, nullptr, nullptr, ND, ND);

        // scores (HMMA, lower-triangular tiles only)
        scores_kernel<<<dim3(8, 8, 64), 256>>>(qhi, qlo, khi, klo, scb);

        // top-k select + softmax + P@V -> ao split
        attn_kernel<<<dim3(16, 64), 256, 81920>>>(scb, vv, aohi, aolo);

        // output projection -> tbuf fp32, LN2 -> h (+split)
        tgemm_kernel<0,0,0,1,0><<<g512, 256, SM_SZ>>>(
            aohi, aolo, lwh + W_O, lwl + W_O, ob + l*ND,
            nullptr, tbuf, nullptr, nullptr, ND, ND);
        ln_kernel<<<NBL, 256>>>(h, tbuf, n2s + l*ND, n2b + l*ND, h, hhi, hlo);

        // FFN1: relu, split-only out
        tgemm_kernel<0,1,0,0,1><<<gdf, 256, SM_SZ>>>(
            hhi, hlo, lwh + W_F1, lwl + W_F1, f1b + l*NDF,
            nullptr, nullptr, mhi, mlo, NDF, ND);

        // FFN2: +residual h; fp32 out (+split for next layer's conv)
        if (l < NE-1) {
            tgemm_kernel<0,0,1,1,1><<<g512, 256, SM_SZ>>>(
                mhi, mlo, lwh + W_F2, lwl + W_F2, f2b + l*ND,
                h, h, hhi, hlo, ND, NDF);
        } else {
            tgemm_kernel<0,0,1,1,0><<<g512, 256, SM_SZ>>>(
                mhi, mlo, lwh + W_F2, lwl + W_F2, f2b + l*ND,
                h, (float*)d_out, nullptr, nullptr, ND, NDF);
        }
    }
}

// round 16
// speedup vs baseline: 1.7006x; 1.0302x over previous
#include <cuda_runtime.h>
#include <cuda_bf16.h>
#include <cstdint>
#include <cstddef>

#define NB 8
#define NL 512
#define ND 512
#define NH 8
#define HD 64
#define NE 4
#define NDF 2048
#define NBL 4096   // NB*NL

#define NEGINF __int_as_float(0xff800000)

// per-layer weight block (bf16, [N][K] layouts)
#define LSTRIDE 3932160
#define W_CONV 0               // [512][1536]
#define W_Q    786432          // [512][512]
#define W_K    1048576
#define W_V    1310720
#define W_O    1572864
#define W_F1   1835008         // [2048][512]
#define W_F2   2883584         // [512][2048]

// smem (bytes): padded rows of 72 bf16 = 144 B (conflict-free ldmatrix)
#define SM_AHI  0
#define SM_ALO  18432          // 128*144
#define SM_BHI  36864
#define SM_BLO  46080          // + 64*144
#define SM_SZ   55296

// ---------------- scratch (static device allocations) ----------------
__device__ float g_h [NBL*ND];
__device__ float g_t [NBL*ND];
__device__ float g_v [NBL*ND];
__device__ float g_sc[(size_t)64*NL*NL];     // [B*H][L][L]
__device__ __nv_bfloat16 g_whi[(size_t)NE*LSTRIDE];
__device__ __nv_bfloat16 g_wlo[(size_t)NE*LSTRIDE];
__device__ __nv_bfloat16 g_hhi[NBL*ND],  g_hlo[NBL*ND];
__device__ __nv_bfloat16 g_qhi[NBL*ND],  g_qlo[NBL*ND];
__device__ __nv_bfloat16 g_khi[NBL*ND],  g_klo[NBL*ND];
__device__ __nv_bfloat16 g_aohi[NBL*ND], g_aolo[NBL*ND];
__device__ __nv_bfloat16 g_mhi[NBL*NDF], g_mlo[NBL*NDF];

// ---------------- helpers ----------------
__device__ __forceinline__ uint32_t smem_u32(const void* p) {
    uint32_t a;
    asm("{ .reg .u64 t; cvta.to.shared.u64 t, %1; cvt.u32.u64 %0, t; }" : "=r"(a) : "l"(p));
    return a;
}
__device__ __forceinline__ void ldsm4(uint32_t* r, uint32_t addr) {
    asm volatile("ldmatrix.sync.aligned.m8n8.x4.shared.b16 {%0,%1,%2,%3}, [%4];"
                 : "=r"(r[0]), "=r"(r[1]), "=r"(r[2]), "=r"(r[3]) : "r"(addr));
}
__device__ __forceinline__ void mma16816(float* c, const uint32_t* a, const uint32_t* b) {
    asm volatile(
        "mma.sync.aligned.m16n8k16.row.col.f32.bf16.bf16.f32 "
        "{%0,%1,%2,%3}, {%4,%5,%6,%7}, {%8,%9}, {%0,%1,%2,%3};"
        : "+f"(c[0]), "+f"(c[1]), "+f"(c[2]), "+f"(c[3])
        : "r"(a[0]), "r"(a[1]), "r"(a[2]), "r"(a[3]), "r"(b[0]), "r"(b[1]));
}
__device__ __forceinline__ void split2(float x, __nv_bfloat16& hi, __nv_bfloat16& lo) {
    hi = __float2bfloat16(x);
    lo = __float2bfloat16(x - __bfloat162float(hi));
}

// ---------------- weight prep: transpose+split [K][N] -> [N][K] bf16 hi/lo -------------
__global__ __launch_bounds__(256) void tsplit_kernel(
    const float* __restrict__ src, __nv_bfloat16* __restrict__ hi,
    __nv_bfloat16* __restrict__ lo, int K, int N,
    size_t src_stride, size_t dst_stride)
{
    __shared__ float tile[32][33];
    int kb = blockIdx.y << 5, nb = blockIdx.x << 5;
    const float* s = src + (size_t)blockIdx.z * src_stride;
    int tx = threadIdx.x, ty = threadIdx.y;   // 32 x 8
    #pragma unroll
    for (int j = 0; j < 4; j++)
        tile[ty + j*8][tx] = s[(size_t)(kb + ty + j*8)*N + nb + tx];
    __syncthreads();
    size_t dbase = (size_t)blockIdx.z * dst_stride;
    #pragma unroll
    for (int j = 0; j < 4; j++) {
        float v = tile[tx][ty + j*8];
        __nv_bfloat16 h_, l_; split2(v, h_, l_);
        size_t o = dbase + (size_t)(nb + ty + j*8)*K + kb + tx;
        hi[o] = h_; lo[o] = l_;
    }
}

// conv weights: w[l][o][i][tap] -> dst[l-block][o][tap*512+i] bf16 hi/lo
__global__ __launch_bounds__(256) void convprep_kernel(
    const float* __restrict__ w, __nv_bfloat16* __restrict__ hi, __nv_bfloat16* __restrict__ lo)
{
    int idx = blockIdx.x * 256 + threadIdx.x;   // 4*512*1536
    int l = idx / (512*1536);
    int r = idx % (512*1536);
    int o = r / 1536;
    int k = r % 1536;
    int tap = k >> 9, i = k & 511;
    float v = w[(((size_t)l*512 + o)*512 + i)*3 + tap];
    __nv_bfloat16 h_, l_; split2(v, h_, l_);
    size_t dst = (size_t)l*LSTRIDE + (size_t)o*1536 + k;
    hi[dst] = h_; lo[dst] = l_;
}

// ---------------- input embedding (also emits bf16 split) ----------------
__global__ __launch_bounds__(256) void embed_kernel(
    const float* __restrict__ x, const float* __restrict__ tf,
    const float* __restrict__ inw, const float* __restrict__ inb,
    const float* __restrict__ pe, const float* __restrict__ tw,
    const float* __restrict__ tb, const float* __restrict__ ps,
    const float* __restrict__ ts, float* __restrict__ out,
    __nv_bfloat16* __restrict__ ohi, __nv_bfloat16* __restrict__ olo)
{
    int bl = blockIdx.x;
    int t  = threadIdx.x;
    __shared__ float xs[64];
    __shared__ float t2[2];
    if (t < 64) xs[t] = x[bl*64 + t];
    if (t < 2)  t2[t] = tf[bl*2 + t];
    __syncthreads();
    float pss = ps[0], tss = ts[0];
    int pos = bl & (NL-1);
    #pragma unroll
    for (int rep = 0; rep < 2; rep++) {
        int d = t + (rep << 8);
        float acc = inb[d];
        #pragma unroll 16
        for (int i = 0; i < 64; i++) acc += xs[i] * inw[i*ND + d];
        acc += pss * pe[pos*ND + d];
        acc += tss * (t2[0]*tw[d] + t2[1]*tw[ND + d] + tb[d]);
        out[bl*ND + d] = acc;
        __nv_bfloat16 h_, l_; split2(acc, h_, l_);
        ohi[bl*ND + d] = h_; olo[bl*ND + d] = l_;
    }
}

// ---------------- HMMA GEMM: 128x64 tile, K-chunks of 64, bf16 3-way split --------------
// Register-prefetch pipelined: LDG chunk c+1 into regs while MMAs run on chunk c.
// 256 threads, 8 warps: wm = wid&3 (32 M-rows), wn = wid>>2 (32 N-cols).
// ASCALE: multiply output by 0.125 before split (folds attention scale into Q).
template<int CONV, int RELU, int ADDRES, int OUTF32, int OUTSPLIT, int ASCALE>
__device__ __forceinline__ void tgemm_body(
    const __nv_bfloat16* __restrict__ Ahi, const __nv_bfloat16* __restrict__ Alo,
    const __nv_bfloat16* __restrict__ Bhi, const __nv_bfloat16* __restrict__ Blo,
    const float* __restrict__ bias, const float* __restrict__ res,
    float* __restrict__ C, __nv_bfloat16* __restrict__ Chi, __nv_bfloat16* __restrict__ Clo,
    int N, int K, int bn, int bm)
{
    extern __shared__ char smem[];
    uint32_t sb = smem_u32(smem);
    int t = threadIdx.x;
    int lane = t & 31, wid = t >> 5;
    int wm = wid & 3, wn = wid >> 2;

    // per-thread load coordinates
    int aRow = t >> 1, aHalf = t & 1;
    int bRow = t >> 2, bQ = t & 3;
    uint32_t aSo = (uint32_t)aRow*144 + (uint32_t)aHalf*64;
    uint32_t bSo = (uint32_t)bRow*144 + (uint32_t)bQ*32;

    // ldmatrix per-lane address pieces
    int sub = lane >> 3, r8 = lane & 7;
    uint32_t aOff = (uint32_t)(wm*32 + (sub & 1)*8 + r8) * 144 + (uint32_t)(sub >> 1) * 16;
    uint32_t bOff = (uint32_t)(wn*32 + (sub >> 1)*8 + r8) * 144 + (uint32_t)(sub & 1) * 16;

    float acc[2][4][4];
    #pragma unroll
    for (int i = 0; i < 2; i++)
        #pragma unroll
        for (int j = 0; j < 4; j++)
            #pragma unroll
            for (int q = 0; q < 4; q++) acc[i][j][q] = 0.f;

    int nk = K >> 6;
    uint4 pa[8];   // A: 4 hi + 4 lo
    uint4 pb[4];   // B: 2 hi + 2 lo

    #define LOAD_REGS(cc)                                                      \
    do {                                                                       \
        int k0_ = (cc) << 6;                                                   \
        const uint4 *ph_, *pl_;                                                \
        bool zero_ = false;                                                    \
        int m_ = bm + aRow;                                                    \
        if (CONV) {                                                            \
            int tap_ = k0_ >> 9;                                               \
            int i0_  = (k0_ & 511) + aHalf*32;                                 \
            zero_ = ((m_ & 511) + tap_ - 2) < 0;                               \
            int rr_ = zero_ ? m_ : (m_ + tap_ - 2);                            \
            ph_ = (const uint4*)&Ahi[(size_t)rr_*512 + i0_];                   \
            pl_ = (const uint4*)&Alo[(size_t)rr_*512 + i0_];                   \
        } else {                                                               \
            ph_ = (const uint4*)&Ahi[(size_t)m_*K + k0_ + aHalf*32];           \
            pl_ = (const uint4*)&Alo[(size_t)m_*K + k0_ + aHalf*32];           \
        }                                                                      \
        _Pragma("unroll")                                                      \
        for (int u = 0; u < 4; u++) {                                          \
            if (zero_) { pa[u] = make_uint4(0,0,0,0); pa[u+4] = make_uint4(0,0,0,0); } \
            else       { pa[u] = ph_[u]; pa[u+4] = pl_[u]; }                   \
        }                                                                      \
        const uint4* sh_ = (const uint4*)&Bhi[(size_t)(bn + bRow)*K + k0_ + bQ*16]; \
        const uint4* sl_ = (const uint4*)&Blo[(size_t)(bn + bRow)*K + k0_ + bQ*16]; \
        pb[0] = sh_[0]; pb[1] = sh_[1]; pb[2] = sl_[0]; pb[3] = sl_[1];        \
    } while (0)

    LOAD_REGS(0);

    for (int c = 0; c < nk; c++) {
        // store prefetched regs to smem
        #pragma unroll
        for (int u = 0; u < 4; u++) {
            *(uint4*)(smem + SM_AHI + aSo + u*16) = pa[u];
            *(uint4*)(smem + SM_ALO + aSo + u*16) = pa[u+4];
        }
        *(uint4*)(smem + SM_BHI + bSo)      = pb[0];
        *(uint4*)(smem + SM_BHI + bSo + 16) = pb[1];
        *(uint4*)(smem + SM_BLO + bSo)      = pb[2];
        *(uint4*)(smem + SM_BLO + bSo + 16) = pb[3];
        __syncthreads();

        // issue next chunk's global loads (latency hidden behind MMA phase)
        if (c + 1 < nk) LOAD_REGS(c + 1);

        #pragma unroll
        for (int ks = 0; ks < 4; ks++) {
            uint32_t ko = ks*32;
            uint32_t ah0[4], ah1[4], al0[4], al1[4];
            uint32_t bh0[4], bh1[4], bl0[4], bl1[4];
            ldsm4(ah0, sb + SM_AHI + aOff + ko);
            ldsm4(ah1, sb + SM_AHI + aOff + 16*144 + ko);
            ldsm4(al0, sb + SM_ALO + aOff + ko);
            ldsm4(al1, sb + SM_ALO + aOff + 16*144 + ko);
            ldsm4(bh0, sb + SM_BHI + bOff + ko);
            ldsm4(bh1, sb + SM_BHI + bOff + 16*144 + ko);
            ldsm4(bl0, sb + SM_BLO + bOff + ko);
            ldsm4(bl1, sb + SM_BLO + bOff + 16*144 + ko);
            #pragma unroll
            for (int mt = 0; mt < 2; mt++) {
                const uint32_t* ah = mt ? ah1 : ah0;
                const uint32_t* al = mt ? al1 : al0;
                #pragma unroll
                for (int nt = 0; nt < 4; nt++) {
                    const uint32_t* bh = ((nt < 2) ? bh0 : bh1) + (nt & 1)*2;
                    const uint32_t* bl = ((nt < 2) ? bl0 : bl1) + (nt & 1)*2;
                    mma16816(acc[mt][nt], ah, bh);
                    mma16816(acc[mt][nt], ah, bl);
                    mma16816(acc[mt][nt], al, bh);
                }
            }
        }
        __syncthreads();
    }
    #undef LOAD_REGS

    // ---- epilogue ----
    int g = lane >> 2, tc = lane & 3;
    #pragma unroll
    for (int mt = 0; mt < 2; mt++) {
        #pragma unroll
        for (int h2 = 0; h2 < 2; h2++) {
            int row = bm + wm*32 + mt*16 + h2*8 + g;
            #pragma unroll
            for (int nt = 0; nt < 4; nt++) {
                int col = bn + wn*32 + nt*8 + tc*2;
                float v0 = acc[mt][nt][h2*2+0] + bias[col];
                float v1 = acc[mt][nt][h2*2+1] + bias[col+1];
                if (RELU) { v0 = fmaxf(v0, 0.f); v1 = fmaxf(v1, 0.f); }
                if (ADDRES) {
                    float2 r2 = *(const float2*)&res[(size_t)row*N + col];
                    v0 += r2.x; v1 += r2.y;
                }
                if (ASCALE) { v0 *= 0.125f; v1 *= 0.125f; }
                if (OUTF32) {
                    float2 o; o.x = v0; o.y = v1;
                    *(float2*)&C[(size_t)row*N + col] = o;
                }
                if (OUTSPLIT) {
                    __nv_bfloat16 h0, l0, h1, l1;
                    split2(v0, h0, l0);
                    split2(v1, h1, l1);
                    __nv_bfloat162 hp; hp.x = h0; hp.y = h1;
                    __nv_bfloat162 lp; lp.x = l0; lp.y = l1;
                    *(__nv_bfloat162*)&Chi[(size_t)row*N + col] = hp;
                    *(__nv_bfloat162*)&Clo[(size_t)row*N + col] = lp;
                }
            }
        }
    }
}

template<int CONV, int RELU, int ADDRES, int OUTF32, int OUTSPLIT>
__global__ __launch_bounds__(256) void tgemm_kernel(
    const __nv_bfloat16* __restrict__ Ahi, const __nv_bfloat16* __restrict__ Alo,
    const __nv_bfloat16* __restrict__ Bhi, const __nv_bfloat16* __restrict__ Blo,
    const float* __restrict__ bias, const float* __restrict__ res,
    float* __restrict__ C, __nv_bfloat16* __restrict__ Chi, __nv_bfloat16* __restrict__ Clo,
    int N, int K)
{
    tgemm_body<CONV, RELU, ADDRES, OUTF32, OUTSPLIT, 0>(
        Ahi, Alo, Bhi, Blo, bias, res, C, Chi, Clo, N, K,
        blockIdx.x << 6, blockIdx.y << 7);
}

// merged Q/K/V projection: z=0 Q (split, pre-scaled by 0.125), z=1 K (split), z=2 V (fp32)
__global__ __launch_bounds__(256) void tgemm_qkv_kernel(
    const __nv_bfloat16* __restrict__ Ahi, const __nv_bfloat16* __restrict__ Alo,
    const __nv_bfloat16* __restrict__ Whi, const __nv_bfloat16* __restrict__ Wlo,
    const float* __restrict__ b0, const float* __restrict__ b1, const float* __restrict__ b2,
    __nv_bfloat16* __restrict__ q_hi, __nv_bfloat16* __restrict__ q_lo,
    __nv_bfloat16* __restrict__ k_hi, __nv_bfloat16* __restrict__ k_lo,
    float* __restrict__ vv)
{
    int z = blockIdx.z;
    const __nv_bfloat16* bh = Whi + (size_t)z * 262144;
    const __nv_bfloat16* bl = Wlo + (size_t)z * 262144;
    if (z == 0) {
        tgemm_body<0, 0, 0, 0, 1, 1>(Ahi, Alo, bh, bl, b0, nullptr, nullptr, q_hi, q_lo,
                                     ND, ND, blockIdx.x << 6, blockIdx.y << 7);
    } else if (z == 1) {
        tgemm_body<0, 0, 0, 0, 1, 0>(Ahi, Alo, bh, bl, b1, nullptr, nullptr, k_hi, k_lo,
                                     ND, ND, blockIdx.x << 6, blockIdx.y << 7);
    } else {
        tgemm_body<0, 0, 0, 1, 0, 0>(Ahi, Alo, bh, bl, b2, nullptr, vv, nullptr, nullptr,
                                     ND, ND, blockIdx.x << 6, blockIdx.y << 7);
    }
}

// ---------------- fused add + LayerNorm (emits fp32 + bf16 split) ----------------
__global__ __launch_bounds__(256) void ln_kernel(
    const float* __restrict__ a, const float* __restrict__ b,
    const float* __restrict__ sc, const float* __restrict__ bi,
    float* __restrict__ out, __nv_bfloat16* __restrict__ ohi, __nv_bfloat16* __restrict__ olo)
{
    int row = blockIdx.x;
    int t = threadIdx.x;
    const float* ar = a + (size_t)row*ND;
    const float* br = b + (size_t)row*ND;
    float v0 = ar[t]       + br[t];
    float v1 = ar[t + 256] + br[t + 256];
    float s1 = v0 + v1;
    float s2 = v0*v0 + v1*v1;
    #pragma unroll
    for (int off = 16; off > 0; off >>= 1) {
        s1 += __shfl_xor_sync(0xffffffffu, s1, off);
        s2 += __shfl_xor_sync(0xffffffffu, s2, off);
    }
    __shared__ float r1[8], r2[8], mv[2];
    int w = t >> 5, lane = t & 31;
    if (lane == 0) { r1[w] = s1; r2[w] = s2; }
    __syncthreads();
    if (t == 0) {
        float a1 = 0.f, a2 = 0.f;
        #pragma unroll
        for (int i = 0; i < 8; i++) { a1 += r1[i]; a2 += r2[i]; }
        float mean = a1 * (1.f/512.f);
        float var  = a2 * (1.f/512.f) - mean*mean;
        mv[0] = mean;
        mv[1] = rsqrtf(var + 1e-5f);
    }
    __syncthreads();
    float mean = mv[0], rstd = mv[1];
    float o0 = (v0 - mean)*rstd*sc[t]       + bi[t];
    float o1 = (v1 - mean)*rstd*sc[t + 256] + bi[t + 256];
    out[(size_t)row*ND + t]       = o0;
    out[(size_t)row*ND + t + 256] = o1;
    __nv_bfloat16 h_, l_;
    split2(o0, h_, l_);
    ohi[(size_t)row*ND + t] = h_;       olo[(size_t)row*ND + t] = l_;
    split2(o1, h_, l_);
    ohi[(size_t)row*ND + t + 256] = h_; olo[(size_t)row*ND + t + 256] = l_;
}

// ---------------- scores (HMMA): per (b,h), lower-tri 64x64 tiles of q @ k^T ----
// Q pre-scaled by 0.125; Q/K in bf16 hi/lo split; 8 warps as 4(M:16) x 2(N:32).
#define SS_QHI 0
#define SS_QLO 9216
#define SS_KHI 18432
#define SS_KLO 27648
__global__ __launch_bounds__(256) void scores_kernel(
    const __nv_bfloat16* __restrict__ q_hi, const __nv_bfloat16* __restrict__ q_lo,
    const __nv_bfloat16* __restrict__ k_hi, const __nv_bfloat16* __restrict__ k_lo,
    float* __restrict__ sc)
{
    int nt = blockIdx.x, mt = blockIdx.y, bh = blockIdx.z;
    if (nt > mt) return;
    int b = bh >> 3, h = bh & 7;
    __shared__ __align__(16) char ssm[36864];
    uint32_t sb = smem_u32(ssm);
    int t = threadIdx.x;
    int lane = t & 31, wid = t >> 5;
    int wm = wid & 3, wn = wid >> 2;

    // load 64x64 bf16 tiles (hi/lo for q and k); thread t: row=t>>2, quarter=t&3 (16 bf16)
    {
        int row = t >> 2, qq = t & 3;
        size_t qbase = ((size_t)(b*NL + mt*64 + row))*ND + h*HD + qq*16;
        size_t kbase = ((size_t)(b*NL + nt*64 + row))*ND + h*HD + qq*16;
        uint32_t so = (uint32_t)row*144 + (uint32_t)qq*32;
        *(uint4*)(ssm + SS_QHI + so)      = *(const uint4*)&q_hi[qbase];
        *(uint4*)(ssm + SS_QHI + so + 16) = *(const uint4*)&q_hi[qbase + 8];
        *(uint4*)(ssm + SS_QLO + so)      = *(const uint4*)&q_lo[qbase];
        *(uint4*)(ssm + SS_QLO + so + 16) = *(const uint4*)&q_lo[qbase + 8];
        *(uint4*)(ssm + SS_KHI + so)      = *(const uint4*)&k_hi[kbase];
        *(uint4*)(ssm + SS_KHI + so + 16) = *(const uint4*)&k_hi[kbase + 8];
        *(uint4*)(ssm + SS_KLO + so)      = *(const uint4*)&k_lo[kbase];
        *(uint4*)(ssm + SS_KLO + so + 16) = *(const uint4*)&k_lo[kbase + 8];
    }
    __syncthreads();

    int sub = lane >> 3, r8 = lane & 7;
    uint32_t aOff = (uint32_t)(wm*16 + (sub & 1)*8 + r8) * 144 + (uint32_t)(sub >> 1) * 16;
    uint32_t bOff = (uint32_t)(wn*32 + (sub >> 1)*8 + r8) * 144 + (uint32_t)(sub & 1) * 16;

    float acc[4][4];
    #pragma unroll
    for (int j = 0; j < 4; j++)
        #pragma unroll
        for (int qx = 0; qx < 4; qx++) acc[j][qx] = 0.f;

    #pragma unroll
    for (int ks = 0; ks < 4; ks++) {
        uint32_t ko = ks*32;
        uint32_t ah[4], al[4];
        uint32_t bh0[4], bh1[4], bl0[4], bl1[4];
        ldsm4(ah,  sb + SS_QHI + aOff + ko);
        ldsm4(al,  sb + SS_QLO + aOff + ko);
        ldsm4(bh0, sb + SS_KHI + bOff + ko);
        ldsm4(bh1, sb + SS_KHI + bOff + 16*144 + ko);
        ldsm4(bl0, sb + SS_KLO + bOff + ko);
        ldsm4(bl1, sb + SS_KLO + bOff + 16*144 + ko);
        #pragma unroll
        for (int ntf = 0; ntf < 4; ntf++) {
            const uint32_t* bhp = ((ntf < 2) ? bh0 : bh1) + (ntf & 1)*2;
            const uint32_t* blp = ((ntf < 2) ? bl0 : bl1) + (ntf & 1)*2;
            mma16816(acc[ntf], ah, bhp);
            mma16816(acc[ntf], ah, blp);
            mma16816(acc[ntf], al, bhp);
        }
    }

    float* base = sc + (size_t)bh*NL*NL;
    int g = lane >> 2, tc = lane & 3;
    #pragma unroll
    for (int h2 = 0; h2 < 2; h2++) {
        int m = mt*64 + wm*16 + h2*8 + g;
        #pragma unroll
        for (int ntf = 0; ntf < 4; ntf++) {
            int col = nt*64 + wn*32 + ntf*8 + tc*2;
            float2 o;
            o.x = acc[ntf][h2*2+0];
            o.y = acc[ntf][h2*2+1];
            *(float2*)&base[(size_t)m*NL + col] = o;
        }
    }
}

// ---------------- top-k(256) select + softmax + P@V (emits ao bf16 split) -----------
// Causal-bounded: only jmax = (qt>>1)+1 64-wide tiles of columns are touched.
__global__ __launch_bounds__(256) void attn_kernel(
    const float* __restrict__ sc, const float* __restrict__ v,
    __nv_bfloat16* __restrict__ aohi, __nv_bfloat16* __restrict__ aolo)
{
    extern __shared__ float sm[];
    float* p  = sm;             // 32*512
    float* vt = sm + 32*512;    // 64*64
    int qt = blockIdx.x, bh = blockIdx.y;
    int b = bh >> 3, h = bh & 7;
    int t = threadIdx.x;
    int jmax = (qt >> 1) + 1;          // valid 64-col tiles
    int c4 = jmax << 4;                // valid float4 columns per row

    // load only the valid score columns (32 rows x jmax*64 cols)
    const float4* s4 = (const float4*)(sc + (size_t)bh*NL*NL + (size_t)(qt*32)*NL);
    float4* p4 = (float4*)p;
    for (int lin = t; lin < (c4 << 5); lin += 256) {
        int row = lin / c4, col = lin % c4;
        p4[row*128 + col] = s4[row*128 + col];
    }
    __syncthreads();

    int w = t >> 5, lane = t & 31;
    for (int rr = 0; rr < 4; rr++) {
        int r  = (w << 2) + rr;
        int qg = (qt << 5) + r;
        int nv = qg + 1;
        float    ev[16];
        unsigned uv[16];
        float    svv[16];
        #pragma unroll
        for (int ii = 0; ii < 16; ii++) {
            int j = lane + (ii << 5);
            bool val = j < nv;
            float s = val ? p[(r << 9) + j] : NEGINF;
            svv[ii] = s;
            unsigned bits = __float_as_uint(s);
            uv[ii] = val ? ((bits & 0x80000000u) ? ~bits : (bits | 0x80000000u)) : 0u;
        }
        unsigned T = 1u;
        if (nv > 256) {
            T = 0u;
            for (int bit = 31; bit >= 0; bit--) {
                unsigned cand = T | (1u << bit);
                int c = 0;
                #pragma unroll
                for (int ii = 0; ii < 16; ii++) c += (uv[ii] >= cand);
                c = __reduce_add_sync(0xffffffffu, c);
                if (c >= 256) T = cand;
            }
        }
        float m = NEGINF;
        #pragma unroll
        for (int ii = 0; ii < 16; ii++)
            if (uv[ii] >= T) m = fmaxf(m, svv[ii]);
        #pragma unroll
        for (int off = 16; off > 0; off >>= 1)
            m = fmaxf(m, __shfl_xor_sync(0xffffffffu, m, off));
        float z = 0.f;
        #pragma unroll
        for (int ii = 0; ii < 16; ii++) {
            float e = (uv[ii] >= T) ? __expf(svv[ii] - m) : 0.f;
            ev[ii] = e;
            z += e;
        }
        #pragma unroll
        for (int off = 16; off > 0; off >>= 1)
            z += __shfl_xor_sync(0xffffffffu, z, off);
        float inv = 1.f / z;
        int iimax = jmax << 1;            // only valid columns get written back
        for (int ii = 0; ii < iimax; ii++) {
            int j = lane + (ii << 5);
            p[(r << 9) + j] = ev[ii] * inv;
        }
    }
    __syncthreads();

    float acc[8] = {};
    int d = t & 63, rb = t >> 6;
    for (int jt = 0; jt < jmax; jt++) {
        const float4* v4 = (const float4*)(v + ((size_t)(b*NL + (jt << 6)))*ND + (h << 6));
        float4* vt4 = (float4*)vt;
        #pragma unroll
        for (int i = 0; i < 4; i++) {
            int lin = t + (i << 8);
            int jr = lin >> 4, d4 = lin & 15;
            vt4[lin] = v4[(size_t)jr*128 + d4];
        }
        __syncthreads();
        #pragma unroll 2
        for (int j = 0; j < 64; j++) {
            float vv = vt[(j << 6) + d];
            int jj = (jt << 6) + j;
            #pragma unroll
            for (int i = 0; i < 8; i++)
                acc[i] += p[((rb + (i << 2)) << 9) + jj] * vv;
        }
        __syncthreads();
    }
    #pragma unroll
    for (int i = 0; i < 8; i++) {
        int row = (qt << 5) + rb + (i << 2);
        size_t idx = ((size_t)(b*NL + row))*ND + (h << 6) + d;
        __nv_bfloat16 h_, l_;
        split2(acc[i], h_, l_);
        aohi[idx] = h_; aolo[idx] = l_;
    }
}

// ---------------- launch ----------------
extern "C" void kernel_launch(void* const* d_in, const int* in_sizes, int n_in,
                              void* d_out, int out_size) {
    const float* x     = (const float*)d_in[0];
    const float* tf    = (const float*)d_in[1];
    const float* in_w  = (const float*)d_in[2];
    const float* in_b  = (const float*)d_in[3];
    const float* pe    = (const float*)d_in[4];
    const float* tw    = (const float*)d_in[5];
    const float* tb    = (const float*)d_in[6];
    const float* ps    = (const float*)d_in[7];
    const float* ts    = (const float*)d_in[8];
    const float* convw = (const float*)d_in[9];
    const float* convb = (const float*)d_in[10];
    const float* qw    = (const float*)d_in[11];
    const float* qb    = (const float*)d_in[12];
    const float* kw    = (const float*)d_in[13];
    const float* kb    = (const float*)d_in[14];
    const float* vw    = (const float*)d_in[15];
    const float* vb    = (const float*)d_in[16];
    const float* ow    = (const float*)d_in[17];
    const float* ob    = (const float*)d_in[18];
    const float* f1w   = (const float*)d_in[19];
    const float* f1b   = (const float*)d_in[20];
    const float* f2w   = (const float*)d_in[21];
    const float* f2b   = (const float*)d_in[22];
    const float* n1s   = (const float*)d_in[23];
    const float* n1b   = (const float*)d_in[24];
    const float* n2s   = (const float*)d_in[25];
    const float* n2b   = (const float*)d_in[26];

    float *h, *tbuf, *vv, *scb;
    __nv_bfloat16 *whi, *wlo, *hhi, *hlo, *qhi, *qlo, *khi, *klo, *aohi, *aolo, *mhi, *mlo;
    cudaGetSymbolAddress((void**)&h,    g_h);
    cudaGetSymbolAddress((void**)&tbuf, g_t);
    cudaGetSymbolAddress((void**)&vv,   g_v);
    cudaGetSymbolAddress((void**)&scb,  g_sc);
    cudaGetSymbolAddress((void**)&whi,  g_whi);
    cudaGetSymbolAddress((void**)&wlo,  g_wlo);
    cudaGetSymbolAddress((void**)&hhi,  g_hhi);
    cudaGetSymbolAddress((void**)&hlo,  g_hlo);
    cudaGetSymbolAddress((void**)&qhi,  g_qhi);
    cudaGetSymbolAddress((void**)&qlo,  g_qlo);
    cudaGetSymbolAddress((void**)&khi,  g_khi);
    cudaGetSymbolAddress((void**)&klo,  g_klo);
    cudaGetSymbolAddress((void**)&aohi, g_aohi);
    cudaGetSymbolAddress((void**)&aolo, g_aolo);
    cudaGetSymbolAddress((void**)&mhi,  g_mhi);
    cudaGetSymbolAddress((void**)&mlo,  g_mlo);

    cudaFuncSetAttribute(attn_kernel, cudaFuncAttributeMaxDynamicSharedMemorySize, 81920);
    cudaFuncSetAttribute(tgemm_kernel<1,0,0,1,0>, cudaFuncAttributeMaxDynamicSharedMemorySize, SM_SZ);
    cudaFuncSetAttribute(tgemm_kernel<0,0,0,1,0>, cudaFuncAttributeMaxDynamicSharedMemorySize, SM_SZ);
    cudaFuncSetAttribute(tgemm_kernel<0,1,0,0,1>, cudaFuncAttributeMaxDynamicSharedMemorySize, SM_SZ);
    cudaFuncSetAttribute(tgemm_kernel<0,0,1,1,1>, cudaFuncAttributeMaxDynamicSharedMemorySize, SM_SZ);
    cudaFuncSetAttribute(tgemm_kernel<0,0,1,1,0>, cudaFuncAttributeMaxDynamicSharedMemorySize, SM_SZ);
    cudaFuncSetAttribute(tgemm_qkv_kernel, cudaFuncAttributeMaxDynamicSharedMemorySize, SM_SZ);

    // ---- weight prep (bf16 split, [N][K]) ----
    convprep_kernel<<<(NE*512*1536)/256, 256>>>(convw, whi, wlo);
    dim3 tb32(32, 8);
    tsplit_kernel<<<dim3(16, 16, 4), tb32>>>(qw,  whi + W_Q,  wlo + W_Q,  512,  512,  262144,  LSTRIDE);
    tsplit_kernel<<<dim3(16, 16, 4), tb32>>>(kw,  whi + W_K,  wlo + W_K,  512,  512,  262144,  LSTRIDE);
    tsplit_kernel<<<dim3(16, 16, 4), tb32>>>(vw,  whi + W_V,  wlo + W_V,  512,  512,  262144,  LSTRIDE);
    tsplit_kernel<<<dim3(16, 16, 4), tb32>>>(ow,  whi + W_O,  wlo + W_O,  512,  512,  262144,  LSTRIDE);
    tsplit_kernel<<<dim3(64, 16, 4), tb32>>>(f1w, whi + W_F1, wlo + W_F1, 512,  2048, 1048576, LSTRIDE);
    tsplit_kernel<<<dim3(16, 64, 4), tb32>>>(f2w, whi + W_F2, wlo + W_F2, 2048, 512,  1048576, LSTRIDE);

    // ---- input embedding ----
    embed_kernel<<<NBL, 256>>>(x, tf, in_w, in_b, pe, tw, tb, ps, ts, h, hhi, hlo);

    dim3 g512(8, 32);         // N=512 tiles
    dim3 gqkv(8, 32, 3);
    dim3 gdf (32, 32);        // N=2048 tiles

    for (int l = 0; l < NE; l++) {
        const __nv_bfloat16* lwh = whi + (size_t)l*LSTRIDE;
        const __nv_bfloat16* lwl = wlo + (size_t)l*LSTRIDE;

        // causal conv (K=1536) -> tbuf fp32, then LN1 -> h (+split)
        tgemm_kernel<1,0,0,1,0><<<g512, 256, SM_SZ>>>(
            hhi, hlo, lwh + W_CONV, lwl + W_CONV, convb + l*ND,
            nullptr, tbuf, nullptr, nullptr, ND, 3*ND);
        ln_kernel<<<NBL, 256>>>(h, tbuf, n1s + l*ND, n1b + l*ND, h, hhi, hlo);

        // Q (scaled split), K (split), V (fp32) projections — one merged launch
        tgemm_qkv_kernel<<<gqkv, 256, SM_SZ>>>(
            hhi, hlo, lwh + W_Q, lwl + W_Q,
            qb + l*ND, kb + l*ND, vb + l*ND, qhi, qlo, khi, klo, vv);

        // scores (HMMA, lower-triangular tiles only)
        scores_kernel<<<dim3(8, 8, 64), 256>>>(qhi, qlo, khi, klo, scb);

        // top-k select + softmax + P@V (causal-bounded) -> ao split
        attn_kernel<<<dim3(16, 64), 256, 81920>>>(scb, vv, aohi, aolo);

        // output projection -> tbuf fp32, LN2 -> h (+split)
        tgemm_kernel<0,0,0,1,0><<<g512, 256, SM_SZ>>>(
            aohi, aolo, lwh + W_O, lwl + W_O, ob + l*ND,
            nullptr, tbuf, nullptr, nullptr, ND, ND);
        ln_kernel<<<NBL, 256>>>(h, tbuf, n2s + l*ND, n2b + l*ND, h, hhi, hlo);

        // FFN1: relu, split-only out
        tgemm_kernel<0,1,0,0,1><<<gdf, 256, SM_SZ>>>(
            hhi, hlo, lwh + W_F1, lwl + W_F1, f1b + l*NDF,
            nullptr, nullptr, mhi, mlo, NDF, ND);

        // FFN2: +residual h; fp32 out (+split for next layer's conv)
        if (l < NE-1) {
            tgemm_kernel<0,0,1,1,1><<<g512, 256, SM_SZ>>>(
                mhi, mlo, lwh + W_F2, lwl + W_F2, f2b + l*ND,
                h, h, hhi, hlo, ND, NDF);
        } else {
            tgemm_kernel<0,0,1,1,0><<<g512, 256, SM_SZ>>>(
                mhi, mlo, lwh + W_F2, lwl + W_F2, f2b + l*ND,
                h, (float*)d_out, nullptr, nullptr, ND, NDF);
        }
    }
}